// round 1
// baseline (speedup 1.0000x reference)
#include <cuda_runtime.h>
#include <math.h>

#define D_MODEL 512
#define N_HEADS 8
#define D_HEAD 64
#define D_FF 2048
#define BATCH 4
#define SEQ 2048
#define M_TOTAL (BATCH * SEQ)   // 8192

// ---------------- scratch (no cudaMalloc allowed) ----------------
__device__ float g_xn1[M_TOTAL * D_MODEL];
__device__ float g_q[M_TOTAL * D_MODEL];
__device__ float g_k[M_TOTAL * D_MODEL];
__device__ float g_v[M_TOTAL * D_MODEL];
__device__ float g_attn[M_TOTAL * D_MODEL];
__device__ float g_x2[M_TOTAL * D_MODEL];
__device__ float g_xn2[M_TOTAL * D_MODEL];
__device__ float g_ffh[M_TOTAL * D_FF];

// ---------------- LayerNorm (row = 512 floats, 128 threads) ----------------
__global__ void ln_kernel(const float* __restrict__ x,
                          const float* __restrict__ g,
                          const float* __restrict__ beta,
                          float* __restrict__ out) {
    int row = blockIdx.x;
    int t = threadIdx.x;             // 128
    const float4* xr = (const float4*)(x + (size_t)row * D_MODEL);
    float4 v = xr[t];
    float s  = v.x + v.y + v.z + v.w;
    float s2 = v.x*v.x + v.y*v.y + v.z*v.z + v.w*v.w;
    #pragma unroll
    for (int o = 16; o; o >>= 1) {
        s  += __shfl_xor_sync(0xffffffffu, s,  o);
        s2 += __shfl_xor_sync(0xffffffffu, s2, o);
    }
    __shared__ float sh[8];
    int w = t >> 5, l = t & 31;
    if (l == 0) { sh[w] = s; sh[4 + w] = s2; }
    __syncthreads();
    s  = sh[0] + sh[1] + sh[2] + sh[3];
    s2 = sh[4] + sh[5] + sh[6] + sh[7];
    float mu  = s * (1.0f / D_MODEL);
    float var = s2 * (1.0f / D_MODEL) - mu * mu;
    float r = rsqrtf(var + 1e-5f);
    float4 gv = ((const float4*)g)[t];
    float4 bv = ((const float4*)beta)[t];
    float4 o;
    o.x = (v.x - mu) * r * gv.x + bv.x;
    o.y = (v.y - mu) * r * gv.y + bv.y;
    o.z = (v.z - mu) * r * gv.z + bv.z;
    o.w = (v.w - mu) * r * gv.w + bv.w;
    ((float4*)(out + (size_t)row * D_MODEL))[t] = o;
}

// x2 = x + attn; xn2 = LN(x2)
__global__ void addln_kernel(const float* __restrict__ x,
                             const float* __restrict__ attn,
                             const float* __restrict__ g,
                             const float* __restrict__ beta,
                             float* __restrict__ x2,
                             float* __restrict__ xn) {
    int row = blockIdx.x;
    int t = threadIdx.x;
    const float4* xr = (const float4*)(x + (size_t)row * D_MODEL);
    const float4* ar = (const float4*)(attn + (size_t)row * D_MODEL);
    float4 a = xr[t], b = ar[t];
    float4 v; v.x = a.x + b.x; v.y = a.y + b.y; v.z = a.z + b.z; v.w = a.w + b.w;
    ((float4*)(x2 + (size_t)row * D_MODEL))[t] = v;
    float s  = v.x + v.y + v.z + v.w;
    float s2 = v.x*v.x + v.y*v.y + v.z*v.z + v.w*v.w;
    #pragma unroll
    for (int o = 16; o; o >>= 1) {
        s  += __shfl_xor_sync(0xffffffffu, s,  o);
        s2 += __shfl_xor_sync(0xffffffffu, s2, o);
    }
    __shared__ float sh[8];
    int w = t >> 5, l = t & 31;
    if (l == 0) { sh[w] = s; sh[4 + w] = s2; }
    __syncthreads();
    s  = sh[0] + sh[1] + sh[2] + sh[3];
    s2 = sh[4] + sh[5] + sh[6] + sh[7];
    float mu  = s * (1.0f / D_MODEL);
    float var = s2 * (1.0f / D_MODEL) - mu * mu;
    float r = rsqrtf(var + 1e-5f);
    float4 gv = ((const float4*)g)[t];
    float4 bv = ((const float4*)beta)[t];
    float4 o;
    o.x = (v.x - mu) * r * gv.x + bv.x;
    o.y = (v.y - mu) * r * gv.y + bv.y;
    o.z = (v.z - mu) * r * gv.z + bv.z;
    o.w = (v.w - mu) * r * gv.w + bv.w;
    ((float4*)(xn + (size_t)row * D_MODEL))[t] = o;
}

// ---------------- Generic 64x64x16 GEMM: C = act(A@W + bias) (+res) ----------------
// A: [M,K] row-major, W: [K,N] row-major. M,N mult of 64, K mult of 16.
template <int RELU, int RES>
__global__ void __launch_bounds__(256) gemm_kernel(
    const float* __restrict__ A, const float* __restrict__ W,
    const float* __restrict__ bias, const float* __restrict__ res,
    float* __restrict__ C, int M, int N, int K) {
    __shared__ float Ast[16][68];   // transposed A tile: Ast[k][m]
    __shared__ float Ws[16][68];
    int tid = threadIdx.x;
    int tx = tid & 15, ty = tid >> 4;
    int row0 = blockIdx.y * 64, col0 = blockIdx.x * 64;

    int ar  = tid >> 2, ac4 = tid & 3;    // A loader: row ar (0..63), f4-col ac4 (0..3)
    int wr  = tid >> 4, wc4 = tid & 15;   // W loader: row wr (0..15), f4-col wc4 (0..15)
    const float* Aptr = A + (size_t)(row0 + ar) * K + 4 * ac4;
    const float* Wptr = W + (size_t)wr * N + col0 + 4 * wc4;

    float acc[4][4] = {};
    for (int k0 = 0; k0 < K; k0 += 16) {
        float4 av = *(const float4*)(Aptr + k0);
        float4 wv = *(const float4*)(Wptr + (size_t)k0 * N);
        __syncthreads();
        Ast[4*ac4+0][ar] = av.x; Ast[4*ac4+1][ar] = av.y;
        Ast[4*ac4+2][ar] = av.z; Ast[4*ac4+3][ar] = av.w;
        *(float4*)&Ws[wr][4*wc4] = wv;
        __syncthreads();
        #pragma unroll
        for (int k = 0; k < 16; k++) {
            float4 a = *(const float4*)&Ast[k][4*ty];
            float4 w = *(const float4*)&Ws[k][4*tx];
            acc[0][0] += a.x*w.x; acc[0][1] += a.x*w.y; acc[0][2] += a.x*w.z; acc[0][3] += a.x*w.w;
            acc[1][0] += a.y*w.x; acc[1][1] += a.y*w.y; acc[1][2] += a.y*w.z; acc[1][3] += a.y*w.w;
            acc[2][0] += a.z*w.x; acc[2][1] += a.z*w.y; acc[2][2] += a.z*w.z; acc[2][3] += a.z*w.w;
            acc[3][0] += a.w*w.x; acc[3][1] += a.w*w.y; acc[3][2] += a.w*w.z; acc[3][3] += a.w*w.w;
        }
    }
    float4 bvec = *(const float4*)&bias[col0 + 4*tx];
    #pragma unroll
    for (int i = 0; i < 4; i++) {
        int r = row0 + 4*ty + i;
        float4 o;
        o.x = acc[i][0] + bvec.x; o.y = acc[i][1] + bvec.y;
        o.z = acc[i][2] + bvec.z; o.w = acc[i][3] + bvec.w;
        if (RELU) {
            o.x = fmaxf(o.x, 0.f); o.y = fmaxf(o.y, 0.f);
            o.z = fmaxf(o.z, 0.f); o.w = fmaxf(o.w, 0.f);
        }
        if (RES) {
            float4 rv = *(const float4*)&res[(size_t)r * N + col0 + 4*tx];
            o.x += rv.x; o.y += rv.y; o.z += rv.z; o.w += rv.w;
        }
        *(float4*)&C[(size_t)r * N + col0 + 4*tx] = o;
    }
}

// ---------------- QKV GEMM with head-permuted store ----------------
// out[(b*H+h)*S + s][dh] ;  blockIdx.z selects Q/K/V.
__global__ void __launch_bounds__(256) qkv_kernel(
    const float* __restrict__ A,
    const float* __restrict__ Wq, const float* __restrict__ bq,
    const float* __restrict__ Wk, const float* __restrict__ bk,
    const float* __restrict__ Wv, const float* __restrict__ bv,
    float* __restrict__ Qo, float* __restrict__ Ko, float* __restrict__ Vo) {
    __shared__ float Ast[16][68];
    __shared__ float Ws[16][68];
    const int K = D_MODEL, N = D_MODEL;
    int z = blockIdx.z;
    const float* W = (z == 0) ? Wq : (z == 1) ? Wk : Wv;
    const float* B = (z == 0) ? bq : (z == 1) ? bk : bv;
    float* O = (z == 0) ? Qo : (z == 1) ? Ko : Vo;

    int tid = threadIdx.x;
    int tx = tid & 15, ty = tid >> 4;
    int row0 = blockIdx.y * 64, col0 = blockIdx.x * 64;
    int ar  = tid >> 2, ac4 = tid & 3;
    int wr  = tid >> 4, wc4 = tid & 15;
    const float* Aptr = A + (size_t)(row0 + ar) * K + 4 * ac4;
    const float* Wptr = W + (size_t)wr * N + col0 + 4 * wc4;

    float acc[4][4] = {};
    for (int k0 = 0; k0 < K; k0 += 16) {
        float4 av = *(const float4*)(Aptr + k0);
        float4 wv = *(const float4*)(Wptr + (size_t)k0 * N);
        __syncthreads();
        Ast[4*ac4+0][ar] = av.x; Ast[4*ac4+1][ar] = av.y;
        Ast[4*ac4+2][ar] = av.z; Ast[4*ac4+3][ar] = av.w;
        *(float4*)&Ws[wr][4*wc4] = wv;
        __syncthreads();
        #pragma unroll
        for (int k = 0; k < 16; k++) {
            float4 a = *(const float4*)&Ast[k][4*ty];
            float4 w = *(const float4*)&Ws[k][4*tx];
            acc[0][0] += a.x*w.x; acc[0][1] += a.x*w.y; acc[0][2] += a.x*w.z; acc[0][3] += a.x*w.w;
            acc[1][0] += a.y*w.x; acc[1][1] += a.y*w.y; acc[1][2] += a.y*w.z; acc[1][3] += a.y*w.w;
            acc[2][0] += a.z*w.x; acc[2][1] += a.z*w.y; acc[2][2] += a.z*w.z; acc[2][3] += a.z*w.w;
            acc[3][0] += a.w*w.x; acc[3][1] += a.w*w.y; acc[3][2] += a.w*w.z; acc[3][3] += a.w*w.w;
        }
    }
    float4 bvec = *(const float4*)&B[col0 + 4*tx];
    int h = col0 >> 6;        // tile spans exactly one head
    #pragma unroll
    for (int i = 0; i < 4; i++) {
        int r = row0 + 4*ty + i;
        int b = r >> 11, s = r & 2047;
        float4 o;
        o.x = acc[i][0] + bvec.x; o.y = acc[i][1] + bvec.y;
        o.z = acc[i][2] + bvec.z; o.w = acc[i][3] + bvec.w;
        *(float4*)&O[((size_t)((b * N_HEADS + h) * SEQ + s)) * D_HEAD + 4*tx] = o;
    }
}

// ---------------- Sigmoid attention: O = sigmoid(QK^T/sqrt(512)) @ V ----------------
// Q,K,V: [B*H][S][64]. Output written directly into [B,S,D] layout.
#define ATT_SCALE 0.044194173824159216f   // 1/sqrt(512)
__global__ void __launch_bounds__(256) attn_kernel(
    const float* __restrict__ Q, const float* __restrict__ K,
    const float* __restrict__ V, float* __restrict__ O) {
    __shared__ float Qs[64][68];
    __shared__ float Ks[32][68];
    __shared__ float Vs[32][68];
    __shared__ float Ss[64][36];

    int bh = blockIdx.y;
    int q0 = blockIdx.x * 64;
    int tid = threadIdx.x;
    int tx = tid & 15, ty = tid >> 4;
    const float* Qb = Q + (size_t)bh * SEQ * D_HEAD;
    const float* Kb = K + (size_t)bh * SEQ * D_HEAD;
    const float* Vb = V + (size_t)bh * SEQ * D_HEAD;

    // load Q tile 64x64 (1024 float4, 4 per thread)
    #pragma unroll
    for (int i = 0; i < 4; i++) {
        int li = tid + 256 * i;
        int r = li >> 4, c4 = li & 15;
        float4 v = *(const float4*)&Qb[(size_t)(q0 + r) * D_HEAD + 4 * c4];
        *(float4*)&Qs[r][4 * c4] = v;
    }
    __syncthreads();

    float acc[4][4] = {};
    for (int t0 = 0; t0 < SEQ; t0 += 32) {
        // load K,V tiles 32x64 (512 f4 each, 2 per thread)
        #pragma unroll
        for (int i = 0; i < 2; i++) {
            int li = tid + 256 * i;
            int r = li >> 4, c4 = li & 15;
            float4 kv = *(const float4*)&Kb[(size_t)(t0 + r) * D_HEAD + 4 * c4];
            float4 vv = *(const float4*)&Vb[(size_t)(t0 + r) * D_HEAD + 4 * c4];
            *(float4*)&Ks[r][4 * c4] = kv;
            *(float4*)&Vs[r][4 * c4] = vv;
        }
        __syncthreads();

        // S = Q @ K^T on this tile: thread owns rows 4ty..+3, cols 2tx..+1
        float sacc[4][2] = {};
        #pragma unroll
        for (int kk = 0; kk < 16; kk++) {
            float4 qv[4], kv[2];
            #pragma unroll
            for (int i = 0; i < 4; i++) qv[i] = *(const float4*)&Qs[4*ty + i][4*kk];
            #pragma unroll
            for (int j = 0; j < 2; j++) kv[j] = *(const float4*)&Ks[2*tx + j][4*kk];
            #pragma unroll
            for (int i = 0; i < 4; i++)
                #pragma unroll
                for (int j = 0; j < 2; j++)
                    sacc[i][j] += qv[i].x*kv[j].x + qv[i].y*kv[j].y
                                + qv[i].z*kv[j].z + qv[i].w*kv[j].w;
        }
        #pragma unroll
        for (int i = 0; i < 4; i++)
            #pragma unroll
            for (int j = 0; j < 2; j++)
                Ss[4*ty + i][2*tx + j] =
                    1.0f / (1.0f + __expf(-sacc[i][j] * ATT_SCALE));
        __syncthreads();

        // O += S @ V : thread owns rows 4ty..+3, cols 4tx..+3
        #pragma unroll
        for (int kk = 0; kk < 8; kk++) {
            float4 sv[4], vv[4];
            #pragma unroll
            for (int i = 0; i < 4; i++) sv[i] = *(const float4*)&Ss[4*ty + i][4*kk];
            #pragma unroll
            for (int q = 0; q < 4; q++) vv[q] = *(const float4*)&Vs[4*kk + q][4*tx];
            #pragma unroll
            for (int i = 0; i < 4; i++) {
                acc[i][0] += sv[i].x*vv[0].x + sv[i].y*vv[1].x + sv[i].z*vv[2].x + sv[i].w*vv[3].x;
                acc[i][1] += sv[i].x*vv[0].y + sv[i].y*vv[1].y + sv[i].z*vv[2].y + sv[i].w*vv[3].y;
                acc[i][2] += sv[i].x*vv[0].z + sv[i].y*vv[1].z + sv[i].z*vv[2].z + sv[i].w*vv[3].z;
                acc[i][3] += sv[i].x*vv[0].w + sv[i].y*vv[1].w + sv[i].z*vv[2].w + sv[i].w*vv[3].w;
            }
        }
        __syncthreads();
    }

    // store into [B,S,D] layout
    int b = bh >> 3, h = bh & 7;
    #pragma unroll
    for (int i = 0; i < 4; i++) {
        int s = q0 + 4*ty + i;
        float4 o;
        o.x = acc[i][0]; o.y = acc[i][1]; o.z = acc[i][2]; o.w = acc[i][3];
        *(float4*)&O[((size_t)(b * SEQ + s)) * D_MODEL + h * D_HEAD + 4*tx] = o;
    }
}

// ---------------- launch ----------------
extern "C" void kernel_launch(void* const* d_in, const int* in_sizes, int n_in,
                              void* d_out, int out_size) {
    const float* x   = (const float*)d_in[0];
    const float* Wq  = (const float*)d_in[1];
    const float* bq  = (const float*)d_in[2];
    const float* Wk  = (const float*)d_in[3];
    const float* bk  = (const float*)d_in[4];
    const float* Wv  = (const float*)d_in[5];
    const float* bv  = (const float*)d_in[6];
    const float* W1  = (const float*)d_in[7];
    const float* b1  = (const float*)d_in[8];
    const float* W2  = (const float*)d_in[9];
    const float* b2  = (const float*)d_in[10];
    const float* g1  = (const float*)d_in[11];
    const float* be1 = (const float*)d_in[12];
    const float* g2  = (const float*)d_in[13];
    const float* be2 = (const float*)d_in[14];
    float* out = (float*)d_out;

    float *p_xn1, *p_q, *p_k, *p_v, *p_attn, *p_x2, *p_xn2, *p_ffh;
    cudaGetSymbolAddress((void**)&p_xn1, g_xn1);
    cudaGetSymbolAddress((void**)&p_q,   g_q);
    cudaGetSymbolAddress((void**)&p_k,   g_k);
    cudaGetSymbolAddress((void**)&p_v,   g_v);
    cudaGetSymbolAddress((void**)&p_attn, g_attn);
    cudaGetSymbolAddress((void**)&p_x2,  g_x2);
    cudaGetSymbolAddress((void**)&p_xn2, g_xn2);
    cudaGetSymbolAddress((void**)&p_ffh, g_ffh);

    // 1. LN1
    ln_kernel<<<M_TOTAL, 128>>>(x, g1, be1, p_xn1);
    // 2. QKV projections (head-permuted outputs)
    qkv_kernel<<<dim3(D_MODEL / 64, M_TOTAL / 64, 3), 256>>>(
        p_xn1, Wq, bq, Wk, bk, Wv, bv, p_q, p_k, p_v);
    // 3. sigmoid attention
    attn_kernel<<<dim3(SEQ / 64, BATCH * N_HEADS), 256>>>(p_q, p_k, p_v, p_attn);
    // 4. residual add + LN2
    addln_kernel<<<M_TOTAL, 128>>>(x, p_attn, g2, be2, p_x2, p_xn2);
    // 5. FFN1: relu(xn2 @ W1 + b1)
    gemm_kernel<1, 0><<<dim3(D_FF / 64, M_TOTAL / 64), 256>>>(
        p_xn2, W1, b1, nullptr, p_ffh, M_TOTAL, D_FF, D_MODEL);
    // 6. FFN2: ffh @ W2 + b2 + x2 -> out
    gemm_kernel<0, 1><<<dim3(D_MODEL / 64, M_TOTAL / 64), 256>>>(
        p_ffh, W2, b2, p_x2, out, M_TOTAL, D_MODEL, D_FF);
}

// round 4
// speedup vs baseline: 1.9930x; 1.9930x over previous
#include <cuda_runtime.h>
#include <cuda_bf16.h>
#include <cstdint>
#include <math.h>

#define D_MODEL 512
#define N_HEADS 8
#define D_HEAD 64
#define D_FF 2048
#define BATCH 4
#define SEQ 2048
#define M_TOTAL (BATCH * SEQ)   // 8192
#define BH (BATCH * N_HEADS)    // 32

typedef __nv_bfloat16 bf16;

// ---------------- scratch (no cudaMalloc allowed) ----------------
__device__ __align__(16) bf16  g_xh[M_TOTAL * D_MODEL];
__device__ __align__(16) bf16  g_xl[M_TOTAL * D_MODEL];
__device__ __align__(16) bf16  g_qh[M_TOTAL * D_MODEL];
__device__ __align__(16) bf16  g_ql[M_TOTAL * D_MODEL];
__device__ __align__(16) bf16  g_kh[M_TOTAL * D_MODEL];
__device__ __align__(16) bf16  g_kl[M_TOTAL * D_MODEL];
__device__ __align__(16) bf16  g_vh[M_TOTAL * D_MODEL];
__device__ __align__(16) bf16  g_vl[M_TOTAL * D_MODEL];
__device__ __align__(16) float g_attn[M_TOTAL * D_MODEL];
__device__ __align__(16) float g_x2[M_TOTAL * D_MODEL];
__device__ __align__(16) bf16  g_x2h[M_TOTAL * D_MODEL];
__device__ __align__(16) bf16  g_x2l[M_TOTAL * D_MODEL];
__device__ __align__(16) bf16  g_fh[M_TOTAL * D_FF];
__device__ __align__(16) bf16  g_fl[M_TOTAL * D_FF];
__device__ __align__(16) bf16  g_wqh[3 * D_MODEL * D_MODEL];
__device__ __align__(16) bf16  g_wql[3 * D_MODEL * D_MODEL];
__device__ __align__(16) bf16  g_w1h[D_FF * D_MODEL];
__device__ __align__(16) bf16  g_w1l[D_FF * D_MODEL];
__device__ __align__(16) bf16  g_w2h[D_MODEL * D_FF];
__device__ __align__(16) bf16  g_w2l[D_MODEL * D_FF];

// ---------------- helpers ----------------
__device__ __forceinline__ uint32_t smem_u32(const void* p) {
    uint32_t a;
    asm("{ .reg .u64 t; cvta.to.shared.u64 t, %1; cvt.u32.u64 %0, t; }" : "=r"(a) : "l"(p));
    return a;
}
__device__ __forceinline__ void cp16(uint32_t dst, const void* src) {
    asm volatile("cp.async.cg.shared.global [%0], [%1], 16;" :: "r"(dst), "l"(src));
}
#define CP_COMMIT() asm volatile("cp.async.commit_group;" ::: "memory")
#define CP_WAIT0()  asm volatile("cp.async.wait_group 0;" ::: "memory")
#define CP_WAIT1()  asm volatile("cp.async.wait_group 1;" ::: "memory")

__device__ __forceinline__ void ldsm4(uint32_t& r0, uint32_t& r1, uint32_t& r2, uint32_t& r3,
                                      uint32_t addr) {
    asm volatile("ldmatrix.sync.aligned.m8n8.x4.shared.b16 {%0,%1,%2,%3}, [%4];"
                 : "=r"(r0), "=r"(r1), "=r"(r2), "=r"(r3) : "r"(addr));
}
__device__ __forceinline__ void ldsm4t(uint32_t& r0, uint32_t& r1, uint32_t& r2, uint32_t& r3,
                                       uint32_t addr) {
    asm volatile("ldmatrix.sync.aligned.m8n8.x4.trans.shared.b16 {%0,%1,%2,%3}, [%4];"
                 : "=r"(r0), "=r"(r1), "=r"(r2), "=r"(r3) : "r"(addr));
}
__device__ __forceinline__ void mma16816(float* d, const uint32_t* a, uint32_t b0, uint32_t b1) {
    asm volatile(
        "mma.sync.aligned.m16n8k16.row.col.f32.bf16.bf16.f32 "
        "{%0,%1,%2,%3},{%4,%5,%6,%7},{%8,%9},{%0,%1,%2,%3};"
        : "+f"(d[0]), "+f"(d[1]), "+f"(d[2]), "+f"(d[3])
        : "r"(a[0]), "r"(a[1]), "r"(a[2]), "r"(a[3]), "r"(b0), "r"(b1));
}

// ---------------- weight transpose + bf16 split ----------------
__global__ void transpose_split_kernel(const float* __restrict__ W, int K, int N,
                                       bf16* __restrict__ oh, bf16* __restrict__ ol) {
    __shared__ float t[32][33];
    int n0 = blockIdx.x * 32, k0 = blockIdx.y * 32;
    int x = threadIdx.x, y = threadIdx.y;   // 32 x 8
    #pragma unroll
    for (int i = 0; i < 4; i++)
        t[y + 8 * i][x] = W[(size_t)(k0 + y + 8 * i) * N + n0 + x];
    __syncthreads();
    #pragma unroll
    for (int i = 0; i < 4; i++) {
        float v = t[x][y + 8 * i];
        bf16 h = __float2bfloat16(v);
        bf16 l = __float2bfloat16(v - __bfloat162float(h));
        size_t o = (size_t)(n0 + y + 8 * i) * K + k0 + x;
        oh[o] = h; ol[o] = l;
    }
}

// ---------------- LayerNorm -> bf16 hi/lo ----------------
__global__ void ln_kernel(const float* __restrict__ x,
                          const float* __restrict__ g,
                          const float* __restrict__ beta,
                          bf16* __restrict__ oh, bf16* __restrict__ ol) {
    int row = blockIdx.x;
    int t = threadIdx.x;             // 128
    float4 v = ((const float4*)(x + (size_t)row * D_MODEL))[t];
    float s  = v.x + v.y + v.z + v.w;
    float s2 = v.x*v.x + v.y*v.y + v.z*v.z + v.w*v.w;
    #pragma unroll
    for (int o = 16; o; o >>= 1) {
        s  += __shfl_xor_sync(0xffffffffu, s,  o);
        s2 += __shfl_xor_sync(0xffffffffu, s2, o);
    }
    __shared__ float sh[8];
    int w = t >> 5, l = t & 31;
    if (l == 0) { sh[w] = s; sh[4 + w] = s2; }
    __syncthreads();
    s  = sh[0] + sh[1] + sh[2] + sh[3];
    s2 = sh[4] + sh[5] + sh[6] + sh[7];
    float mu  = s * (1.0f / D_MODEL);
    float var = s2 * (1.0f / D_MODEL) - mu * mu;
    float r = rsqrtf(var + 1e-5f);
    float4 gv = ((const float4*)g)[t];
    float4 bv = ((const float4*)beta)[t];
    float o4[4];
    o4[0] = (v.x - mu) * r * gv.x + bv.x;
    o4[1] = (v.y - mu) * r * gv.y + bv.y;
    o4[2] = (v.z - mu) * r * gv.z + bv.z;
    o4[3] = (v.w - mu) * r * gv.w + bv.w;
    size_t base = (size_t)row * D_MODEL + 4 * t;
    #pragma unroll
    for (int i = 0; i < 4; i++) {
        bf16 h = __float2bfloat16(o4[i]);
        oh[base + i] = h;
        ol[base + i] = __float2bfloat16(o4[i] - __bfloat162float(h));
    }
}

__global__ void addln_kernel(const float* __restrict__ x,
                             const float* __restrict__ attn,
                             const float* __restrict__ g,
                             const float* __restrict__ beta,
                             float* __restrict__ x2,
                             bf16* __restrict__ oh, bf16* __restrict__ ol) {
    int row = blockIdx.x;
    int t = threadIdx.x;
    float4 a = ((const float4*)(x + (size_t)row * D_MODEL))[t];
    float4 b = ((const float4*)(attn + (size_t)row * D_MODEL))[t];
    float4 v; v.x = a.x + b.x; v.y = a.y + b.y; v.z = a.z + b.z; v.w = a.w + b.w;
    ((float4*)(x2 + (size_t)row * D_MODEL))[t] = v;
    float s  = v.x + v.y + v.z + v.w;
    float s2 = v.x*v.x + v.y*v.y + v.z*v.z + v.w*v.w;
    #pragma unroll
    for (int o = 16; o; o >>= 1) {
        s  += __shfl_xor_sync(0xffffffffu, s,  o);
        s2 += __shfl_xor_sync(0xffffffffu, s2, o);
    }
    __shared__ float sh[8];
    int w = t >> 5, l = t & 31;
    if (l == 0) { sh[w] = s; sh[4 + w] = s2; }
    __syncthreads();
    s  = sh[0] + sh[1] + sh[2] + sh[3];
    s2 = sh[4] + sh[5] + sh[6] + sh[7];
    float mu  = s * (1.0f / D_MODEL);
    float var = s2 * (1.0f / D_MODEL) - mu * mu;
    float r = rsqrtf(var + 1e-5f);
    float4 gv = ((const float4*)g)[t];
    float4 bv = ((const float4*)beta)[t];
    float o4[4];
    o4[0] = (v.x - mu) * r * gv.x + bv.x;
    o4[1] = (v.y - mu) * r * gv.y + bv.y;
    o4[2] = (v.z - mu) * r * gv.z + bv.z;
    o4[3] = (v.w - mu) * r * gv.w + bv.w;
    size_t base = (size_t)row * D_MODEL + 4 * t;
    #pragma unroll
    for (int i = 0; i < 4; i++) {
        bf16 h = __float2bfloat16(o4[i]);
        oh[base + i] = h;
        ol[base + i] = __float2bfloat16(o4[i] - __bfloat162float(h));
    }
}

// ---------------- mma.sync GEMM ----------------
// C[M,Ntot] = (Ahi+Alo)[M,K] @ (Bhi+Blo)[Ntot,K]^T  (HH+HL+LH)
// CTA tile 128x128, 8 warps (2x4), warp 64x32, K-chunk 32, 2-stage cp.async.
// smem per stage: mats {Ah,Al,Bh,Bl}, each 2 k16-chunks of [128 rows][48B].
#define GCH   (128 * 48)          // one k16 chunk
#define GMAT  (2 * GCH)           // one matrix per stage (2 chunks)
#define GSTAGE (4 * GMAT)         // 49152
#define GSMEM (2 * GSTAGE)        // 98304

// MODE 0: +qkv bias, store bf16 hi/lo q/k/v head-permuted
// MODE 1: +bias, relu, store bf16 hi/lo
// MODE 2: +bias +res, store fp32
template <int MODE>
__global__ void __launch_bounds__(256) mma_gemm_kernel(
    const bf16* __restrict__ Ahi, const bf16* __restrict__ Alo,
    const bf16* __restrict__ Bhi, const bf16* __restrict__ Blo,
    int Kdim,
    const float* __restrict__ b0, const float* __restrict__ b1, const float* __restrict__ b2,
    const float* __restrict__ res,
    float* __restrict__ o32,
    bf16* __restrict__ oh0, bf16* __restrict__ ol0,
    bf16* __restrict__ oh1, bf16* __restrict__ ol1,
    bf16* __restrict__ oh2, bf16* __restrict__ ol2)
{
    extern __shared__ char smem[];
    uint32_t sb = smem_u32(smem);
    int tid = threadIdx.x, wid = tid >> 5, lane = tid & 31;
    int wr = wid >> 2, wc = wid & 3;
    int m0 = blockIdx.y * 128, n0 = blockIdx.x * 128;
    const bf16* srcs[4] = {Ahi, Alo, Bhi, Blo};

    // loader: 2048 x 16B per stage
    auto load_stage = [&](int c, int s) {
        #pragma unroll
        for (int i = 0; i < 8; i++) {
            int idx = i * 256 + tid;
            int mat = idx >> 9;
            int rem = idx & 511;
            int row = rem >> 2;
            int q = rem & 3, kk = q >> 1, half = q & 1;
            const bf16* src = srcs[mat] +
                (size_t)(((mat < 2) ? m0 : n0) + row) * Kdim + c * 32 + kk * 16 + half * 8;
            uint32_t dst = sb + s * GSTAGE + mat * GMAT + kk * GCH + row * 48 + half * 16;
            cp16(dst, src);
        }
    };

    float acc[4][4][4];
    #pragma unroll
    for (int a = 0; a < 4; a++)
        #pragma unroll
        for (int b = 0; b < 4; b++)
            #pragma unroll
            for (int cc = 0; cc < 4; cc++) acc[a][b][cc] = 0.f;

    load_stage(0, 0);
    CP_COMMIT();

    int arow = lane & 15, ahalf = lane >> 4;
    int brow = (lane & 7) + ((lane >> 4) << 3), bhalf = (lane >> 3) & 1;
    int nc = Kdim >> 5;
    for (int c = 0; c < nc; c++) {
        int s = c & 1;
        if (c + 1 < nc) { load_stage(c + 1, s ^ 1); CP_COMMIT(); CP_WAIT1(); }
        else CP_WAIT0();
        __syncthreads();

        #pragma unroll
        for (int kk = 0; kk < 2; kk++) {
            uint32_t abase = sb + s * GSTAGE + kk * GCH;
            uint32_t ah[4][4], al[4][4];
            #pragma unroll
            for (int mt = 0; mt < 4; mt++) {
                uint32_t ad = abase + (uint32_t)(wr * 64 + mt * 16 + arow) * 48 + ahalf * 16;
                ldsm4(ah[mt][0], ah[mt][1], ah[mt][2], ah[mt][3], ad);
                ldsm4(al[mt][0], al[mt][1], al[mt][2], al[mt][3], ad + GMAT);
            }
            uint32_t bh[2][4], bl[2][4];
            #pragma unroll
            for (int p = 0; p < 2; p++) {
                uint32_t bd = sb + s * GSTAGE + 2 * GMAT + kk * GCH +
                              (uint32_t)(wc * 32 + p * 16 + brow) * 48 + bhalf * 16;
                ldsm4(bh[p][0], bh[p][1], bh[p][2], bh[p][3], bd);
                ldsm4(bl[p][0], bl[p][1], bl[p][2], bl[p][3], bd + GMAT);
            }
            #pragma unroll
            for (int mt = 0; mt < 4; mt++)
                #pragma unroll
                for (int nt = 0; nt < 4; nt++) {
                    uint32_t hb0 = bh[nt >> 1][(nt & 1) * 2], hb1 = bh[nt >> 1][(nt & 1) * 2 + 1];
                    uint32_t lb0 = bl[nt >> 1][(nt & 1) * 2], lb1 = bl[nt >> 1][(nt & 1) * 2 + 1];
                    mma16816(acc[mt][nt], ah[mt], hb0, hb1);
                    mma16816(acc[mt][nt], ah[mt], lb0, lb1);
                    mma16816(acc[mt][nt], al[mt], hb0, hb1);
                }
        }
        __syncthreads();
    }

    // epilogue
    #pragma unroll
    for (int mt = 0; mt < 4; mt++) {
        int r0 = m0 + wr * 64 + mt * 16 + (lane >> 2);
        #pragma unroll
        for (int nt = 0; nt < 4; nt++) {
            int nglob = n0 + wc * 32 + nt * 8 + (lane & 3) * 2;
            if (MODE == 0) {
                int z = nglob >> 9;
                int nn = nglob & 511;
                int h = nn >> 6, dh = nn & 63;
                const float* bias = (z == 0) ? b0 : (z == 1) ? b1 : b2;
                bf16* OH = (z == 0) ? oh0 : (z == 1) ? oh1 : oh2;
                bf16* OL = (z == 0) ? ol0 : (z == 1) ? ol1 : ol2;
                float bv0 = bias[nn], bv1 = bias[nn + 1];
                #pragma unroll
                for (int j = 0; j < 2; j++) {
                    int r = r0 + j * 8;
                    int bb = r >> 11, sidx = r & 2047;
                    size_t dst = ((size_t)((bb * N_HEADS + h) * SEQ + sidx)) * D_HEAD + dh;
                    float v0 = acc[mt][nt][2 * j] + bv0;
                    float v1 = acc[mt][nt][2 * j + 1] + bv1;
                    bf16 h0 = __float2bfloat16(v0), h1 = __float2bfloat16(v1);
                    __nv_bfloat162 hp; hp.x = h0; hp.y = h1;
                    __nv_bfloat162 lp;
                    lp.x = __float2bfloat16(v0 - __bfloat162float(h0));
                    lp.y = __float2bfloat16(v1 - __bfloat162float(h1));
                    *(__nv_bfloat162*)(OH + dst) = hp;
                    *(__nv_bfloat162*)(OL + dst) = lp;
                }
            } else if (MODE == 1) {
                float bv0 = b0[nglob], bv1 = b0[nglob + 1];
                #pragma unroll
                for (int j = 0; j < 2; j++) {
                    int r = r0 + j * 8;
                    size_t dst = (size_t)r * D_FF + nglob;
                    float v0 = fmaxf(acc[mt][nt][2 * j] + bv0, 0.f);
                    float v1 = fmaxf(acc[mt][nt][2 * j + 1] + bv1, 0.f);
                    bf16 h0 = __float2bfloat16(v0), h1 = __float2bfloat16(v1);
                    __nv_bfloat162 hp; hp.x = h0; hp.y = h1;
                    __nv_bfloat162 lp;
                    lp.x = __float2bfloat16(v0 - __bfloat162float(h0));
                    lp.y = __float2bfloat16(v1 - __bfloat162float(h1));
                    *(__nv_bfloat162*)(oh0 + dst) = hp;
                    *(__nv_bfloat162*)(ol0 + dst) = lp;
                }
            } else {
                float bv0 = b0[nglob], bv1 = b0[nglob + 1];
                #pragma unroll
                for (int j = 0; j < 2; j++) {
                    int r = r0 + j * 8;
                    size_t dst = (size_t)r * D_MODEL + nglob;
                    float2 rv = *(const float2*)(res + dst);
                    float2 ov;
                    ov.x = acc[mt][nt][2 * j] + bv0 + rv.x;
                    ov.y = acc[mt][nt][2 * j + 1] + bv1 + rv.y;
                    *(float2*)(o32 + dst) = ov;
                }
            }
        }
    }
}

// ---------------- fused sigmoid attention (mma.sync bf16, split) ----------------
// Per CTA: one 128-row Q tile of one (b,h); stream K/V in 64-key tiles.
#define ACH   (128 * 48)            // S/Q k16 chunk
#define KCH   (64 * 48)             // K/V k16 chunk
#define QOFF  0                     // Qh 4*ACH, Ql 4*ACH  -> 49152
#define KVOFF 49152                 // per stage: Kh,Kl,Vh,Vl each 4*KCH=12288 -> 49152/stage
#define KVSTG 49152
#define SOFF  (49152 + 2 * KVSTG)   // Sh 4*ACH, Sl 4*ACH -> 49152
#define ASMEM (SOFF + 49152)        // 196608
#define ATT_SCALE 0.044194173824159216f   // 1/sqrt(512)

__global__ void __launch_bounds__(256) attn_kernel(
    const bf16* __restrict__ Qh, const bf16* __restrict__ Ql,
    const bf16* __restrict__ Kh, const bf16* __restrict__ Kl,
    const bf16* __restrict__ Vh, const bf16* __restrict__ Vl,
    float* __restrict__ O)
{
    extern __shared__ char smem[];
    uint32_t sb = smem_u32(smem);
    int tid = threadIdx.x, wid = tid >> 5, lane = tid & 31;
    int wr = wid >> 2, wc = wid & 3;
    int bh = blockIdx.y;
    int q0 = blockIdx.x * 128;
    size_t bhbase = (size_t)bh * SEQ * D_HEAD;

    // load Q (hi+lo) resident: 2048 x 16B
    {
        const bf16* qs[2] = {Qh, Ql};
        #pragma unroll
        for (int i = 0; i < 8; i++) {
            int idx = i * 256 + tid;
            int mat = idx >> 10;
            int rem = idx & 1023;
            int row = rem >> 3;
            int q = rem & 7, cc = q >> 1, half = q & 1;
            const bf16* src = qs[mat] + bhbase + (size_t)(q0 + row) * D_HEAD + cc * 16 + half * 8;
            uint32_t dst = sb + QOFF + mat * (4 * ACH) + cc * ACH + row * 48 + half * 16;
            cp16(dst, src);
        }
    }

    const bf16* kvs[4] = {Kh, Kl, Vh, Vl};
    auto load_kv = [&](int t0, int s) {
        #pragma unroll
        for (int i = 0; i < 8; i++) {
            int idx = i * 256 + tid;
            int mat = idx >> 9;
            int rem = idx & 511;
            int row = rem >> 3;
            int q = rem & 7, cc = q >> 1, half = q & 1;
            const bf16* src = kvs[mat] + bhbase + (size_t)(t0 + row) * D_HEAD + cc * 16 + half * 8;
            uint32_t dst = sb + KVOFF + s * KVSTG + mat * (4 * KCH) + cc * KCH + row * 48 + half * 16;
            cp16(dst, src);
        }
    };

    load_kv(0, 0);
    CP_COMMIT();

    float oacc[4][2][4];
    #pragma unroll
    for (int a = 0; a < 4; a++)
        #pragma unroll
        for (int b = 0; b < 2; b++)
            #pragma unroll
            for (int cc = 0; cc < 4; cc++) oacc[a][b][cc] = 0.f;

    int arow = lane & 15, ahalf = lane >> 4;
    int brow = (lane & 7) + ((lane >> 4) << 3), bhalf = (lane >> 3) & 1;
    const int niter = SEQ / 64;
    for (int c = 0; c < niter; c++) {
        int s = c & 1;
        if (c + 1 < niter) { load_kv((c + 1) * 64, s ^ 1); CP_COMMIT(); CP_WAIT1(); }
        else CP_WAIT0();
        __syncthreads();

        // ---- S = Q @ K^T (warp: 64 q x 16 keys) ----
        float sacc[4][2][4];
        #pragma unroll
        for (int a = 0; a < 4; a++)
            #pragma unroll
            for (int b = 0; b < 2; b++)
                #pragma unroll
                for (int cc = 0; cc < 4; cc++) sacc[a][b][cc] = 0.f;

        #pragma unroll
        for (int cc = 0; cc < 4; cc++) {
            uint32_t ah[4][4], al[4][4];
            #pragma unroll
            for (int mt = 0; mt < 4; mt++) {
                uint32_t ad = sb + QOFF + cc * ACH +
                              (uint32_t)(wr * 64 + mt * 16 + arow) * 48 + ahalf * 16;
                ldsm4(ah[mt][0], ah[mt][1], ah[mt][2], ah[mt][3], ad);
                ldsm4(al[mt][0], al[mt][1], al[mt][2], al[mt][3], ad + 4 * ACH);
            }
            uint32_t kbh[4], kbl[4];
            {
                uint32_t bd = sb + KVOFF + s * KVSTG + cc * KCH +
                              (uint32_t)(wc * 16 + brow) * 48 + bhalf * 16;
                ldsm4(kbh[0], kbh[1], kbh[2], kbh[3], bd);
                ldsm4(kbl[0], kbl[1], kbl[2], kbl[3], bd + 4 * KCH);
            }
            #pragma unroll
            for (int mt = 0; mt < 4; mt++)
                #pragma unroll
                for (int nt = 0; nt < 2; nt++) {
                    uint32_t hb0 = kbh[nt * 2], hb1 = kbh[nt * 2 + 1];
                    uint32_t lb0 = kbl[nt * 2], lb1 = kbl[nt * 2 + 1];
                    mma16816(sacc[mt][nt], ah[mt], hb0, hb1);
                    mma16816(sacc[mt][nt], ah[mt], lb0, lb1);
                    mma16816(sacc[mt][nt], al[mt], hb0, hb1);
                }
        }

        // ---- sigmoid + split -> smem S ----
        #pragma unroll
        for (int mt = 0; mt < 4; mt++)
            #pragma unroll
            for (int nt = 0; nt < 2; nt++) {
                int col = wc * 16 + nt * 8 + (lane & 3) * 2;
                int cc = col >> 4, half = (col >> 3) & 1, off = (col & 7) * 2;
                #pragma unroll
                for (int j = 0; j < 2; j++) {
                    int srow = wr * 64 + mt * 16 + (lane >> 2) + j * 8;
                    float v0 = 1.0f / (1.0f + __expf(-sacc[mt][nt][2 * j] * ATT_SCALE));
                    float v1 = 1.0f / (1.0f + __expf(-sacc[mt][nt][2 * j + 1] * ATT_SCALE));
                    bf16 h0 = __float2bfloat16(v0), h1 = __float2bfloat16(v1);
                    __nv_bfloat162 hp; hp.x = h0; hp.y = h1;
                    __nv_bfloat162 lp;
                    lp.x = __float2bfloat16(v0 - __bfloat162float(h0));
                    lp.y = __float2bfloat16(v1 - __bfloat162float(h1));
                    uint32_t ad = sb + SOFF + cc * ACH + (uint32_t)srow * 48 + half * 16 + off;
                    *(__nv_bfloat162*)(smem + (ad - sb)) = hp;
                    *(__nv_bfloat162*)(smem + (ad - sb) + 4 * ACH) = lp;
                }
            }
        __syncthreads();

        // ---- O += S @ V (warp: 64 q x 16 dims) ----
        #pragma unroll
        for (int cc = 0; cc < 4; cc++) {    // key chunks (mma-k)
            uint32_t sh_[4][4], sl_[4][4];
            #pragma unroll
            for (int mt = 0; mt < 4; mt++) {
                uint32_t ad = sb + SOFF + cc * ACH +
                              (uint32_t)(wr * 64 + mt * 16 + arow) * 48 + ahalf * 16;
                ldsm4(sh_[mt][0], sh_[mt][1], sh_[mt][2], sh_[mt][3], ad);
                ldsm4(sl_[mt][0], sl_[mt][1], sl_[mt][2], sl_[mt][3], ad + 4 * ACH);
            }
            uint32_t vbh[4], vbl[4];
            {
                // trans ldsm: key = cc*16 + (lane&15), dim-half select = lane>>4
                uint32_t ad = sb + KVOFF + s * KVSTG + 2 * (4 * KCH) + wc * KCH +
                              (uint32_t)(cc * 16 + (lane & 15)) * 48 + (lane >> 4) * 16;
                ldsm4t(vbh[0], vbh[1], vbh[2], vbh[3], ad);
                ldsm4t(vbl[0], vbl[1], vbl[2], vbl[3], ad + 4 * KCH);
            }
            #pragma unroll
            for (int mt = 0; mt < 4; mt++)
                #pragma unroll
                for (int nt = 0; nt < 2; nt++) {
                    uint32_t hb0 = vbh[nt * 2], hb1 = vbh[nt * 2 + 1];
                    uint32_t lb0 = vbl[nt * 2], lb1 = vbl[nt * 2 + 1];
                    mma16816(oacc[mt][nt], sh_[mt], hb0, hb1);
                    mma16816(oacc[mt][nt], sh_[mt], lb0, lb1);
                    mma16816(oacc[mt][nt], sl_[mt], hb0, hb1);
                }
        }
        __syncthreads();
    }

    // epilogue: write [B,S,D]
    int b = bh >> 3, h = bh & 7;
    #pragma unroll
    for (int mt = 0; mt < 4; mt++)
        #pragma unroll
        for (int nt = 0; nt < 2; nt++) {
            int dim = h * D_HEAD + wc * 16 + nt * 8 + (lane & 3) * 2;
            #pragma unroll
            for (int j = 0; j < 2; j++) {
                int srow = q0 + wr * 64 + mt * 16 + (lane >> 2) + j * 8;
                float2 ov;
                ov.x = oacc[mt][nt][2 * j];
                ov.y = oacc[mt][nt][2 * j + 1];
                *(float2*)(O + (size_t)(b * SEQ + srow) * D_MODEL + dim) = ov;
            }
        }
}

// ---------------- launch ----------------
extern "C" void kernel_launch(void* const* d_in, const int* in_sizes, int n_in,
                              void* d_out, int out_size) {
    const float* x   = (const float*)d_in[0];
    const float* Wq  = (const float*)d_in[1];
    const float* bq  = (const float*)d_in[2];
    const float* Wk  = (const float*)d_in[3];
    const float* bk  = (const float*)d_in[4];
    const float* Wv  = (const float*)d_in[5];
    const float* bv  = (const float*)d_in[6];
    const float* W1  = (const float*)d_in[7];
    const float* b1  = (const float*)d_in[8];
    const float* W2  = (const float*)d_in[9];
    const float* b2  = (const float*)d_in[10];
    const float* g1  = (const float*)d_in[11];
    const float* be1 = (const float*)d_in[12];
    const float* g2  = (const float*)d_in[13];
    const float* be2 = (const float*)d_in[14];
    float* out = (float*)d_out;

    bf16 *p_xh, *p_xl, *p_x2h, *p_x2l, *p_fh, *p_fl;
    bf16 *p_qh, *p_ql, *p_kh, *p_kl, *p_vh, *p_vl;
    bf16 *p_wqh, *p_wql, *p_w1h, *p_w1l, *p_w2h, *p_w2l;
    float *p_attn, *p_x2;
    cudaGetSymbolAddress((void**)&p_xh, g_xh);
    cudaGetSymbolAddress((void**)&p_xl, g_xl);
    cudaGetSymbolAddress((void**)&p_qh, g_qh);
    cudaGetSymbolAddress((void**)&p_ql, g_ql);
    cudaGetSymbolAddress((void**)&p_kh, g_kh);
    cudaGetSymbolAddress((void**)&p_kl, g_kl);
    cudaGetSymbolAddress((void**)&p_vh, g_vh);
    cudaGetSymbolAddress((void**)&p_vl, g_vl);
    cudaGetSymbolAddress((void**)&p_attn, g_attn);
    cudaGetSymbolAddress((void**)&p_x2, g_x2);
    cudaGetSymbolAddress((void**)&p_x2h, g_x2h);
    cudaGetSymbolAddress((void**)&p_x2l, g_x2l);
    cudaGetSymbolAddress((void**)&p_fh, g_fh);
    cudaGetSymbolAddress((void**)&p_fl, g_fl);
    cudaGetSymbolAddress((void**)&p_wqh, g_wqh);
    cudaGetSymbolAddress((void**)&p_wql, g_wql);
    cudaGetSymbolAddress((void**)&p_w1h, g_w1h);
    cudaGetSymbolAddress((void**)&p_w1l, g_w1l);
    cudaGetSymbolAddress((void**)&p_w2h, g_w2h);
    cudaGetSymbolAddress((void**)&p_w2l, g_w2l);

    cudaFuncSetAttribute(mma_gemm_kernel<0>, cudaFuncAttributeMaxDynamicSharedMemorySize, GSMEM);
    cudaFuncSetAttribute(mma_gemm_kernel<1>, cudaFuncAttributeMaxDynamicSharedMemorySize, GSMEM);
    cudaFuncSetAttribute(mma_gemm_kernel<2>, cudaFuncAttributeMaxDynamicSharedMemorySize, GSMEM);
    cudaFuncSetAttribute(attn_kernel, cudaFuncAttributeMaxDynamicSharedMemorySize, ASMEM);

    dim3 tb(32, 8);
    transpose_split_kernel<<<dim3(D_MODEL/32, D_MODEL/32), tb>>>(Wq, D_MODEL, D_MODEL, p_wqh, p_wql);
    transpose_split_kernel<<<dim3(D_MODEL/32, D_MODEL/32), tb>>>(Wk, D_MODEL, D_MODEL, p_wqh + D_MODEL*D_MODEL, p_wql + D_MODEL*D_MODEL);
    transpose_split_kernel<<<dim3(D_MODEL/32, D_MODEL/32), tb>>>(Wv, D_MODEL, D_MODEL, p_wqh + 2*D_MODEL*D_MODEL, p_wql + 2*D_MODEL*D_MODEL);
    transpose_split_kernel<<<dim3(D_FF/32, D_MODEL/32), tb>>>(W1, D_MODEL, D_FF, p_w1h, p_w1l);
    transpose_split_kernel<<<dim3(D_MODEL/32, D_FF/32), tb>>>(W2, D_FF, D_MODEL, p_w2h, p_w2l);

    // 1. LN1 -> bf16 hi/lo
    ln_kernel<<<M_TOTAL, 128>>>(x, g1, be1, p_xh, p_xl);
    // 2. QKV: bf16 hi/lo head-permuted outputs
    mma_gemm_kernel<0><<<dim3(3*D_MODEL/128, M_TOTAL/128), 256, GSMEM>>>(
        p_xh, p_xl, p_wqh, p_wql, D_MODEL, bq, bk, bv, nullptr, nullptr,
        p_qh, p_ql, p_kh, p_kl, p_vh, p_vl);
    // 3. fused sigmoid attention
    attn_kernel<<<dim3(SEQ/128, BH), 256, ASMEM>>>(
        p_qh, p_ql, p_kh, p_kl, p_vh, p_vl, p_attn);
    // 4. residual + LN2
    addln_kernel<<<M_TOTAL, 128>>>(x, p_attn, g2, be2, p_x2, p_x2h, p_x2l);
    // 5. FFN1: relu(xn2 @ W1 + b1) -> bf16 hi/lo
    mma_gemm_kernel<1><<<dim3(D_FF/128, M_TOTAL/128), 256, GSMEM>>>(
        p_x2h, p_x2l, p_w1h, p_w1l, D_MODEL, b1, nullptr, nullptr, nullptr, nullptr,
        p_fh, p_fl, nullptr, nullptr, nullptr, nullptr);
    // 6. FFN2: ffh @ W2 + b2 + x2 -> out
    mma_gemm_kernel<2><<<dim3(D_MODEL/128, M_TOTAL/128), 256, GSMEM>>>(
        p_fh, p_fl, p_w2h, p_w2l, D_FF, b2, nullptr, nullptr, p_x2, out,
        nullptr, nullptr, nullptr, nullptr, nullptr, nullptr);
}

// round 9
// speedup vs baseline: 2.5350x; 1.2720x over previous
#include <cuda_runtime.h>
#include <cuda_bf16.h>
#include <cstdint>
#include <math.h>

#define D_MODEL 512
#define N_HEADS 8
#define D_HEAD 64
#define D_FF 2048
#define BATCH 4
#define SEQ 2048
#define M_TOTAL (BATCH * SEQ)   // 8192
#define BH (BATCH * N_HEADS)    // 32

typedef __nv_bfloat16 bf16;

// ---------------- scratch (no cudaMalloc allowed) ----------------
__device__ __align__(16) bf16  g_xh[M_TOTAL * D_MODEL];
__device__ __align__(16) bf16  g_xl[M_TOTAL * D_MODEL];
__device__ __align__(16) bf16  g_qh[M_TOTAL * D_MODEL];
__device__ __align__(16) bf16  g_ql[M_TOTAL * D_MODEL];
__device__ __align__(16) bf16  g_kh[M_TOTAL * D_MODEL];
__device__ __align__(16) bf16  g_kl[M_TOTAL * D_MODEL];
__device__ __align__(16) bf16  g_vh[M_TOTAL * D_MODEL];
__device__ __align__(16) bf16  g_vl[M_TOTAL * D_MODEL];
__device__ __align__(16) float g_attn[M_TOTAL * D_MODEL];
__device__ __align__(16) float g_x2[M_TOTAL * D_MODEL];
__device__ __align__(16) bf16  g_x2h[M_TOTAL * D_MODEL];
__device__ __align__(16) bf16  g_x2l[M_TOTAL * D_MODEL];
__device__ __align__(16) bf16  g_fh[M_TOTAL * D_FF];
__device__ __align__(16) bf16  g_fl[M_TOTAL * D_FF];
__device__ __align__(16) bf16  g_wqh[3 * D_MODEL * D_MODEL];
__device__ __align__(16) bf16  g_wql[3 * D_MODEL * D_MODEL];
__device__ __align__(16) bf16  g_w1h[D_FF * D_MODEL];
__device__ __align__(16) bf16  g_w1l[D_FF * D_MODEL];
__device__ __align__(16) bf16  g_w2h[D_MODEL * D_FF];
__device__ __align__(16) bf16  g_w2l[D_MODEL * D_FF];

// ---------------- helpers ----------------
__device__ __forceinline__ uint32_t smem_u32(const void* p) {
    uint32_t a;
    asm("{ .reg .u64 t; cvta.to.shared.u64 t, %1; cvt.u32.u64 %0, t; }" : "=r"(a) : "l"(p));
    return a;
}
__device__ __forceinline__ void cp16(uint32_t dst, const void* src) {
    asm volatile("cp.async.cg.shared.global [%0], [%1], 16;" :: "r"(dst), "l"(src));
}
#define CP_COMMIT() asm volatile("cp.async.commit_group;" ::: "memory")
#define CP_WAIT0()  asm volatile("cp.async.wait_group 0;" ::: "memory")
#define CP_WAIT1()  asm volatile("cp.async.wait_group 1;" ::: "memory")

__device__ __forceinline__ void ldsm4(uint32_t* r, uint32_t addr) {
    asm volatile("ldmatrix.sync.aligned.m8n8.x4.shared.b16 {%0,%1,%2,%3}, [%4];"
                 : "=r"(r[0]), "=r"(r[1]), "=r"(r[2]), "=r"(r[3]) : "r"(addr));
}
__device__ __forceinline__ void ldsm4t(uint32_t* r, uint32_t addr) {
    asm volatile("ldmatrix.sync.aligned.m8n8.x4.trans.shared.b16 {%0,%1,%2,%3}, [%4];"
                 : "=r"(r[0]), "=r"(r[1]), "=r"(r[2]), "=r"(r[3]) : "r"(addr));
}
__device__ __forceinline__ void mma16816(float* d, const uint32_t* a, uint32_t b0, uint32_t b1) {
    asm volatile(
        "mma.sync.aligned.m16n8k16.row.col.f32.bf16.bf16.f32 "
        "{%0,%1,%2,%3},{%4,%5,%6,%7},{%8,%9},{%0,%1,%2,%3};"
        : "+f"(d[0]), "+f"(d[1]), "+f"(d[2]), "+f"(d[3])
        : "r"(a[0]), "r"(a[1]), "r"(a[2]), "r"(a[3]), "r"(b0), "r"(b1));
}
__device__ __forceinline__ float sigmoid_fast(float xhalf) {
    // sigmoid(x) = 0.5*tanh(x/2)+0.5 ; caller passes x/2 already scaled
    float t;
    asm("tanh.approx.f32 %0, %1;" : "=f"(t) : "f"(xhalf));
    return fmaf(t, 0.5f, 0.5f);
}
__device__ __forceinline__ void split_pack(float v0, float v1, uint32_t& hp, uint32_t& lp) {
    bf16 h0 = __float2bfloat16(v0), h1 = __float2bfloat16(v1);
    __nv_bfloat162 h2; h2.x = h0; h2.y = h1;
    hp = *(uint32_t*)&h2;
    __nv_bfloat162 l2;
    l2.x = __float2bfloat16(v0 - __bfloat162float(h0));
    l2.y = __float2bfloat16(v1 - __bfloat162float(h1));
    lp = *(uint32_t*)&l2;
}

// ---------------- weight transpose + bf16 split ----------------
__global__ void transpose_split_kernel(const float* __restrict__ W, int K, int N,
                                       bf16* __restrict__ oh, bf16* __restrict__ ol) {
    __shared__ float t[32][33];
    int n0 = blockIdx.x * 32, k0 = blockIdx.y * 32;
    int x = threadIdx.x, y = threadIdx.y;   // 32 x 8
    #pragma unroll
    for (int i = 0; i < 4; i++)
        t[y + 8 * i][x] = W[(size_t)(k0 + y + 8 * i) * N + n0 + x];
    __syncthreads();
    #pragma unroll
    for (int i = 0; i < 4; i++) {
        float v = t[x][y + 8 * i];
        bf16 h = __float2bfloat16(v);
        bf16 l = __float2bfloat16(v - __bfloat162float(h));
        size_t o = (size_t)(n0 + y + 8 * i) * K + k0 + x;
        oh[o] = h; ol[o] = l;
    }
}

// ---------------- LayerNorm -> bf16 hi/lo ----------------
__global__ void ln_kernel(const float* __restrict__ x,
                          const float* __restrict__ g,
                          const float* __restrict__ beta,
                          bf16* __restrict__ oh, bf16* __restrict__ ol) {
    int row = blockIdx.x;
    int t = threadIdx.x;             // 128
    float4 v = ((const float4*)(x + (size_t)row * D_MODEL))[t];
    float s  = v.x + v.y + v.z + v.w;
    float s2 = v.x*v.x + v.y*v.y + v.z*v.z + v.w*v.w;
    #pragma unroll
    for (int o = 16; o; o >>= 1) {
        s  += __shfl_xor_sync(0xffffffffu, s,  o);
        s2 += __shfl_xor_sync(0xffffffffu, s2, o);
    }
    __shared__ float sh[8];
    int w = t >> 5, l = t & 31;
    if (l == 0) { sh[w] = s; sh[4 + w] = s2; }
    __syncthreads();
    s  = sh[0] + sh[1] + sh[2] + sh[3];
    s2 = sh[4] + sh[5] + sh[6] + sh[7];
    float mu  = s * (1.0f / D_MODEL);
    float var = s2 * (1.0f / D_MODEL) - mu * mu;
    float r = rsqrtf(var + 1e-5f);
    float4 gv = ((const float4*)g)[t];
    float4 bv = ((const float4*)beta)[t];
    float o4[4];
    o4[0] = (v.x - mu) * r * gv.x + bv.x;
    o4[1] = (v.y - mu) * r * gv.y + bv.y;
    o4[2] = (v.z - mu) * r * gv.z + bv.z;
    o4[3] = (v.w - mu) * r * gv.w + bv.w;
    size_t base = (size_t)row * D_MODEL + 4 * t;
    #pragma unroll
    for (int i = 0; i < 4; i++) {
        bf16 h = __float2bfloat16(o4[i]);
        oh[base + i] = h;
        ol[base + i] = __float2bfloat16(o4[i] - __bfloat162float(h));
    }
}

__global__ void addln_kernel(const float* __restrict__ x,
                             const float* __restrict__ attn,
                             const float* __restrict__ g,
                             const float* __restrict__ beta,
                             float* __restrict__ x2,
                             bf16* __restrict__ oh, bf16* __restrict__ ol) {
    int row = blockIdx.x;
    int t = threadIdx.x;
    float4 a = ((const float4*)(x + (size_t)row * D_MODEL))[t];
    float4 b = ((const float4*)(attn + (size_t)row * D_MODEL))[t];
    float4 v; v.x = a.x + b.x; v.y = a.y + b.y; v.z = a.z + b.z; v.w = a.w + b.w;
    ((float4*)(x2 + (size_t)row * D_MODEL))[t] = v;
    float s  = v.x + v.y + v.z + v.w;
    float s2 = v.x*v.x + v.y*v.y + v.z*v.z + v.w*v.w;
    #pragma unroll
    for (int o = 16; o; o >>= 1) {
        s  += __shfl_xor_sync(0xffffffffu, s,  o);
        s2 += __shfl_xor_sync(0xffffffffu, s2, o);
    }
    __shared__ float sh[8];
    int w = t >> 5, l = t & 31;
    if (l == 0) { sh[w] = s; sh[4 + w] = s2; }
    __syncthreads();
    s  = sh[0] + sh[1] + sh[2] + sh[3];
    s2 = sh[4] + sh[5] + sh[6] + sh[7];
    float mu  = s * (1.0f / D_MODEL);
    float var = s2 * (1.0f / D_MODEL) - mu * mu;
    float r = rsqrtf(var + 1e-5f);
    float4 gv = ((const float4*)g)[t];
    float4 bv = ((const float4*)beta)[t];
    float o4[4];
    o4[0] = (v.x - mu) * r * gv.x + bv.x;
    o4[1] = (v.y - mu) * r * gv.y + bv.y;
    o4[2] = (v.z - mu) * r * gv.z + bv.z;
    o4[3] = (v.w - mu) * r * gv.w + bv.w;
    size_t base = (size_t)row * D_MODEL + 4 * t;
    #pragma unroll
    for (int i = 0; i < 4; i++) {
        bf16 h = __float2bfloat16(o4[i]);
        oh[base + i] = h;
        ol[base + i] = __float2bfloat16(o4[i] - __bfloat162float(h));
    }
}

// ---------------- mma.sync GEMM (unchanged) ----------------
#define GCH   (128 * 48)
#define GMAT  (2 * GCH)
#define GSTAGE (4 * GMAT)
#define GSMEM (2 * GSTAGE)

template <int MODE>
__global__ void __launch_bounds__(256) mma_gemm_kernel(
    const bf16* __restrict__ Ahi, const bf16* __restrict__ Alo,
    const bf16* __restrict__ Bhi, const bf16* __restrict__ Blo,
    int Kdim,
    const float* __restrict__ b0, const float* __restrict__ b1, const float* __restrict__ b2,
    const float* __restrict__ res,
    float* __restrict__ o32,
    bf16* __restrict__ oh0, bf16* __restrict__ ol0,
    bf16* __restrict__ oh1, bf16* __restrict__ ol1,
    bf16* __restrict__ oh2, bf16* __restrict__ ol2)
{
    extern __shared__ char smem[];
    uint32_t sb = smem_u32(smem);
    int tid = threadIdx.x, wid = tid >> 5, lane = tid & 31;
    int wr = wid >> 2, wc = wid & 3;
    int m0 = blockIdx.y * 128, n0 = blockIdx.x * 128;
    const bf16* srcs[4] = {Ahi, Alo, Bhi, Blo};

    auto load_stage = [&](int c, int s) {
        #pragma unroll
        for (int i = 0; i < 8; i++) {
            int idx = i * 256 + tid;
            int mat = idx >> 9;
            int rem = idx & 511;
            int row = rem >> 2;
            int q = rem & 3, kk = q >> 1, half = q & 1;
            const bf16* src = srcs[mat] +
                (size_t)(((mat < 2) ? m0 : n0) + row) * Kdim + c * 32 + kk * 16 + half * 8;
            uint32_t dst = sb + s * GSTAGE + mat * GMAT + kk * GCH + row * 48 + half * 16;
            cp16(dst, src);
        }
    };

    float acc[4][4][4];
    #pragma unroll
    for (int a = 0; a < 4; a++)
        #pragma unroll
        for (int b = 0; b < 4; b++)
            #pragma unroll
            for (int cc = 0; cc < 4; cc++) acc[a][b][cc] = 0.f;

    load_stage(0, 0);
    CP_COMMIT();

    int arow = lane & 15, ahalf = lane >> 4;
    int brow = (lane & 7) + ((lane >> 4) << 3), bhalf = (lane >> 3) & 1;
    int nc = Kdim >> 5;
    for (int c = 0; c < nc; c++) {
        int s = c & 1;
        if (c + 1 < nc) { load_stage(c + 1, s ^ 1); CP_COMMIT(); CP_WAIT1(); }
        else CP_WAIT0();
        __syncthreads();

        #pragma unroll
        for (int kk = 0; kk < 2; kk++) {
            uint32_t abase = sb + s * GSTAGE + kk * GCH;
            uint32_t ah[4][4], al[4][4];
            #pragma unroll
            for (int mt = 0; mt < 4; mt++) {
                uint32_t ad = abase + (uint32_t)(wr * 64 + mt * 16 + arow) * 48 + ahalf * 16;
                ldsm4(ah[mt], ad);
                ldsm4(al[mt], ad + GMAT);
            }
            uint32_t bh[2][4], bl[2][4];
            #pragma unroll
            for (int p = 0; p < 2; p++) {
                uint32_t bd = sb + s * GSTAGE + 2 * GMAT + kk * GCH +
                              (uint32_t)(wc * 32 + p * 16 + brow) * 48 + bhalf * 16;
                ldsm4(bh[p], bd);
                ldsm4(bl[p], bd + GMAT);
            }
            #pragma unroll
            for (int mt = 0; mt < 4; mt++)
                #pragma unroll
                for (int nt = 0; nt < 4; nt++) {
                    uint32_t hb0 = bh[nt >> 1][(nt & 1) * 2], hb1 = bh[nt >> 1][(nt & 1) * 2 + 1];
                    uint32_t lb0 = bl[nt >> 1][(nt & 1) * 2], lb1 = bl[nt >> 1][(nt & 1) * 2 + 1];
                    mma16816(acc[mt][nt], ah[mt], hb0, hb1);
                    mma16816(acc[mt][nt], ah[mt], lb0, lb1);
                    mma16816(acc[mt][nt], al[mt], hb0, hb1);
                }
        }
        __syncthreads();
    }

    #pragma unroll
    for (int mt = 0; mt < 4; mt++) {
        int r0 = m0 + wr * 64 + mt * 16 + (lane >> 2);
        #pragma unroll
        for (int nt = 0; nt < 4; nt++) {
            int nglob = n0 + wc * 32 + nt * 8 + (lane & 3) * 2;
            if (MODE == 0) {
                int z = nglob >> 9;
                int nn = nglob & 511;
                int h = nn >> 6, dh = nn & 63;
                const float* bias = (z == 0) ? b0 : (z == 1) ? b1 : b2;
                bf16* OH = (z == 0) ? oh0 : (z == 1) ? oh1 : oh2;
                bf16* OL = (z == 0) ? ol0 : (z == 1) ? ol1 : ol2;
                float bv0 = bias[nn], bv1 = bias[nn + 1];
                #pragma unroll
                for (int j = 0; j < 2; j++) {
                    int r = r0 + j * 8;
                    int bb = r >> 11, sidx = r & 2047;
                    size_t dst = ((size_t)((bb * N_HEADS + h) * SEQ + sidx)) * D_HEAD + dh;
                    float v0 = acc[mt][nt][2 * j] + bv0;
                    float v1 = acc[mt][nt][2 * j + 1] + bv1;
                    uint32_t hp, lp;
                    split_pack(v0, v1, hp, lp);
                    *(uint32_t*)(OH + dst) = hp;
                    *(uint32_t*)(OL + dst) = lp;
                }
            } else if (MODE == 1) {
                float bv0 = b0[nglob], bv1 = b0[nglob + 1];
                #pragma unroll
                for (int j = 0; j < 2; j++) {
                    int r = r0 + j * 8;
                    size_t dst = (size_t)r * D_FF + nglob;
                    float v0 = fmaxf(acc[mt][nt][2 * j] + bv0, 0.f);
                    float v1 = fmaxf(acc[mt][nt][2 * j + 1] + bv1, 0.f);
                    uint32_t hp, lp;
                    split_pack(v0, v1, hp, lp);
                    *(uint32_t*)(oh0 + dst) = hp;
                    *(uint32_t*)(ol0 + dst) = lp;
                }
            } else {
                float bv0 = b0[nglob], bv1 = b0[nglob + 1];
                #pragma unroll
                for (int j = 0; j < 2; j++) {
                    int r = r0 + j * 8;
                    size_t dst = (size_t)r * D_MODEL + nglob;
                    float2 rv = *(const float2*)(res + dst);
                    float2 ov;
                    ov.x = acc[mt][nt][2 * j] + bv0 + rv.x;
                    ov.y = acc[mt][nt][2 * j + 1] + bv1 + rv.y;
                    *(float2*)(o32 + dst) = ov;
                }
            }
        }
    }
}

// ---------------- fused sigmoid attention: register S-reuse ----------------
// 8 warps = 4 q-groups (32 rows) x 2 key-groups (32 keys/iter).
// Q in smem (resident), K/V double-buffered 64-key stages, S never leaves regs.
#define AKCH  (64 * 48)              // one k16 chunk of K or V (64 rows x 48B)
#define AKMAT (4 * AKCH)             // 12288: one matrix (4 d-chunks)
#define AKSTG (4 * AKMAT)            // 49152: Kh,Kl,Vh,Vl
#define AQOFF (2 * AKSTG)            // 98304: Q region
#define AQCH  (128 * 48)             // 6144
#define AQMAT (4 * AQCH)             // 24576 per mat (hi, lo)
#define ASMEM (AQOFF + 2 * AQMAT)    // 147456
// tanh arg scale = 0.5 / sqrt(512)
#define ATT_HSCALE 0.022097086912079608f

__global__ void __launch_bounds__(256) attn_kernel(
    const bf16* __restrict__ Qh, const bf16* __restrict__ Ql,
    const bf16* __restrict__ Kh, const bf16* __restrict__ Kl,
    const bf16* __restrict__ Vh, const bf16* __restrict__ Vl,
    float* __restrict__ O)
{
    extern __shared__ char smem[];
    uint32_t sb = smem_u32(smem);
    int tid = threadIdx.x, wid = tid >> 5, lane = tid & 31;
    int wq = wid >> 1, wk = wid & 1;
    int bh = blockIdx.y;
    int q0 = blockIdx.x * 128;
    size_t bhbase = (size_t)bh * SEQ * D_HEAD;

    // stage Q (hi+lo) into smem: 2048 cp16
    {
        const bf16* qs[2] = {Qh, Ql};
        #pragma unroll
        for (int i = 0; i < 8; i++) {
            int idx = i * 256 + tid;
            int mat = idx >> 10;
            int rem = idx & 1023;
            int row = rem >> 3;
            int q = rem & 7, cc = q >> 1, half = q & 1;
            const bf16* src = qs[mat] + bhbase + (size_t)(q0 + row) * D_HEAD + cc * 16 + half * 8;
            uint32_t dst = sb + AQOFF + mat * AQMAT + cc * AQCH + row * 48 + half * 16;
            cp16(dst, src);
        }
    }

    const bf16* kvs[4] = {Kh, Kl, Vh, Vl};
    auto load_kv = [&](int t0, int s) {
        #pragma unroll
        for (int i = 0; i < 8; i++) {
            int idx = i * 256 + tid;
            int mat = idx >> 9;
            int rem = idx & 511;
            int row = rem >> 3;
            int q = rem & 7, cc = q >> 1, half = q & 1;
            const bf16* src = kvs[mat] + bhbase + (size_t)(t0 + row) * D_HEAD + cc * 16 + half * 8;
            uint32_t dst = sb + s * AKSTG + mat * AKMAT + cc * AKCH + row * 48 + half * 16;
            cp16(dst, src);
        }
    };

    load_kv(0, 0);
    CP_COMMIT();

    float oacc[2][8][4];
    #pragma unroll
    for (int a = 0; a < 2; a++)
        #pragma unroll
        for (int b = 0; b < 8; b++)
            #pragma unroll
            for (int cc = 0; cc < 4; cc++) oacc[a][b][cc] = 0.f;

    int arow = lane & 15, ahalf = lane >> 4;
    int brow = (lane & 7) + ((lane >> 4) << 3), bhalf = (lane >> 3) & 1;
    const int niter = SEQ / 64;
    for (int c = 0; c < niter; c++) {
        int s = c & 1;
        if (c + 1 < niter) { load_kv((c + 1) * 64, s ^ 1); CP_COMMIT(); CP_WAIT1(); }
        else CP_WAIT0();
        __syncthreads();

        // ---- S = Q @ K^T (warp: 32 q x 32 keys) ----
        float sacc[2][4][4];
        #pragma unroll
        for (int a = 0; a < 2; a++)
            #pragma unroll
            for (int b = 0; b < 4; b++)
                #pragma unroll
                for (int cc = 0; cc < 4; cc++) sacc[a][b][cc] = 0.f;

        #pragma unroll
        for (int cc = 0; cc < 4; cc++) {
            uint32_t qah[2][4], qal[2][4];
            #pragma unroll
            for (int mt = 0; mt < 2; mt++) {
                uint32_t ad = sb + AQOFF + cc * AQCH +
                              (uint32_t)(wq * 32 + mt * 16 + arow) * 48 + ahalf * 16;
                ldsm4(qah[mt], ad);
                ldsm4(qal[mt], ad + AQMAT);
            }
            uint32_t kbh[2][4], kbl[2][4];
            #pragma unroll
            for (int p = 0; p < 2; p++) {
                uint32_t bd = sb + s * AKSTG + cc * AKCH +
                              (uint32_t)(wk * 32 + p * 16 + brow) * 48 + bhalf * 16;
                ldsm4(kbh[p], bd);
                ldsm4(kbl[p], bd + AKMAT);
            }
            #pragma unroll
            for (int mt = 0; mt < 2; mt++)
                #pragma unroll
                for (int nt = 0; nt < 4; nt++) {
                    int p = nt >> 1, i0 = (nt & 1) * 2;
                    mma16816(sacc[mt][nt], qah[mt], kbh[p][i0], kbh[p][i0 + 1]);
                    mma16816(sacc[mt][nt], qah[mt], kbl[p][i0], kbl[p][i0 + 1]);
                    mma16816(sacc[mt][nt], qal[mt], kbh[p][i0], kbh[p][i0 + 1]);
                }
        }

        // ---- sigmoid in regs, C-frag -> A-frag repack (no smem) ----
        #pragma unroll
        for (int mt = 0; mt < 2; mt++)
            #pragma unroll
            for (int nt = 0; nt < 4; nt++)
                #pragma unroll
                for (int i = 0; i < 4; i++)
                    sacc[mt][nt][i] = sigmoid_fast(sacc[mt][nt][i] * ATT_HSCALE);

        // A-frag register order: a0=(row,k0-7), a1=(row+8,k0-7), a2=(row,k8-15), a3=(row+8,k8-15)
        // C tile 2kc supplies k0-7 (c0c1=row, c2c3=row+8); tile 2kc+1 supplies k8-15.
        uint32_t Sh[2][2][4], Sl[2][2][4];
        #pragma unroll
        for (int mt = 0; mt < 2; mt++)
            #pragma unroll
            for (int kc = 0; kc < 2; kc++) {
                split_pack(sacc[mt][2*kc][0],   sacc[mt][2*kc][1],   Sh[mt][kc][0], Sl[mt][kc][0]);
                split_pack(sacc[mt][2*kc][2],   sacc[mt][2*kc][3],   Sh[mt][kc][1], Sl[mt][kc][1]);
                split_pack(sacc[mt][2*kc+1][0], sacc[mt][2*kc+1][1], Sh[mt][kc][2], Sl[mt][kc][2]);
                split_pack(sacc[mt][2*kc+1][2], sacc[mt][2*kc+1][3], Sh[mt][kc][3], Sl[mt][kc][3]);
            }

        // ---- O += S @ V (warp: 32 q x 64 dims over its 32 keys) ----
        #pragma unroll
        for (int kc = 0; kc < 2; kc++) {
            #pragma unroll
            for (int dg = 0; dg < 4; dg++) {
                uint32_t vbh[4], vbl[4];
                uint32_t vad = sb + s * AKSTG + 2 * AKMAT + dg * AKCH +
                               (uint32_t)(wk * 32 + kc * 16 + (lane & 15)) * 48 + (lane >> 4) * 16;
                ldsm4t(vbh, vad);
                ldsm4t(vbl, vad + AKMAT);
                #pragma unroll
                for (int mt = 0; mt < 2; mt++)
                    #pragma unroll
                    for (int nt2 = 0; nt2 < 2; nt2++) {
                        float* o = oacc[mt][dg * 2 + nt2];
                        mma16816(o, Sh[mt][kc], vbh[nt2 * 2], vbh[nt2 * 2 + 1]);
                        mma16816(o, Sh[mt][kc], vbl[nt2 * 2], vbl[nt2 * 2 + 1]);
                        mma16816(o, Sl[mt][kc], vbh[nt2 * 2], vbh[nt2 * 2 + 1]);
                    }
            }
        }
        __syncthreads();
    }

    // ---- combine the two key-group partials, write [B,S,D] ----
    if (wk == 1) {
        #pragma unroll
        for (int mt = 0; mt < 2; mt++)
            #pragma unroll
            for (int nt = 0; nt < 8; nt++)
                #pragma unroll
                for (int j = 0; j < 2; j++) {
                    int r = mt * 16 + (lane >> 2) + j * 8;
                    int col = nt * 8 + (lane & 3) * 2;
                    float2 p; p.x = oacc[mt][nt][2 * j]; p.y = oacc[mt][nt][2 * j + 1];
                    *(float2*)(smem + wq * 8192 + r * 256 + col * 4) = p;
                }
    }
    __syncthreads();
    if (wk == 0) {
        int b = bh >> 3, h = bh & 7;
        #pragma unroll
        for (int mt = 0; mt < 2; mt++)
            #pragma unroll
            for (int nt = 0; nt < 8; nt++)
                #pragma unroll
                for (int j = 0; j < 2; j++) {
                    int r = mt * 16 + (lane >> 2) + j * 8;
                    int col = nt * 8 + (lane & 3) * 2;
                    float2 p = *(const float2*)(smem + wq * 8192 + r * 256 + col * 4);
                    float2 o;
                    o.x = oacc[mt][nt][2 * j] + p.x;
                    o.y = oacc[mt][nt][2 * j + 1] + p.y;
                    *(float2*)(O + (size_t)(b * SEQ + q0 + wq * 32 + r) * D_MODEL + h * D_HEAD + col) = o;
                }
    }
}

// ---------------- launch ----------------
extern "C" void kernel_launch(void* const* d_in, const int* in_sizes, int n_in,
                              void* d_out, int out_size) {
    const float* x   = (const float*)d_in[0];
    const float* Wq  = (const float*)d_in[1];
    const float* bq  = (const float*)d_in[2];
    const float* Wk  = (const float*)d_in[3];
    const float* bk  = (const float*)d_in[4];
    const float* Wv  = (const float*)d_in[5];
    const float* bv  = (const float*)d_in[6];
    const float* W1  = (const float*)d_in[7];
    const float* b1  = (const float*)d_in[8];
    const float* W2  = (const float*)d_in[9];
    const float* b2  = (const float*)d_in[10];
    const float* g1  = (const float*)d_in[11];
    const float* be1 = (const float*)d_in[12];
    const float* g2  = (const float*)d_in[13];
    const float* be2 = (const float*)d_in[14];
    float* out = (float*)d_out;

    bf16 *p_xh, *p_xl, *p_x2h, *p_x2l, *p_fh, *p_fl;
    bf16 *p_qh, *p_ql, *p_kh, *p_kl, *p_vh, *p_vl;
    bf16 *p_wqh, *p_wql, *p_w1h, *p_w1l, *p_w2h, *p_w2l;
    float *p_attn, *p_x2;
    cudaGetSymbolAddress((void**)&p_xh, g_xh);
    cudaGetSymbolAddress((void**)&p_xl, g_xl);
    cudaGetSymbolAddress((void**)&p_qh, g_qh);
    cudaGetSymbolAddress((void**)&p_ql, g_ql);
    cudaGetSymbolAddress((void**)&p_kh, g_kh);
    cudaGetSymbolAddress((void**)&p_kl, g_kl);
    cudaGetSymbolAddress((void**)&p_vh, g_vh);
    cudaGetSymbolAddress((void**)&p_vl, g_vl);
    cudaGetSymbolAddress((void**)&p_attn, g_attn);
    cudaGetSymbolAddress((void**)&p_x2, g_x2);
    cudaGetSymbolAddress((void**)&p_x2h, g_x2h);
    cudaGetSymbolAddress((void**)&p_x2l, g_x2l);
    cudaGetSymbolAddress((void**)&p_fh, g_fh);
    cudaGetSymbolAddress((void**)&p_fl, g_fl);
    cudaGetSymbolAddress((void**)&p_wqh, g_wqh);
    cudaGetSymbolAddress((void**)&p_wql, g_wql);
    cudaGetSymbolAddress((void**)&p_w1h, g_w1h);
    cudaGetSymbolAddress((void**)&p_w1l, g_w1l);
    cudaGetSymbolAddress((void**)&p_w2h, g_w2h);
    cudaGetSymbolAddress((void**)&p_w2l, g_w2l);

    cudaFuncSetAttribute(mma_gemm_kernel<0>, cudaFuncAttributeMaxDynamicSharedMemorySize, GSMEM);
    cudaFuncSetAttribute(mma_gemm_kernel<1>, cudaFuncAttributeMaxDynamicSharedMemorySize, GSMEM);
    cudaFuncSetAttribute(mma_gemm_kernel<2>, cudaFuncAttributeMaxDynamicSharedMemorySize, GSMEM);
    cudaFuncSetAttribute(attn_kernel, cudaFuncAttributeMaxDynamicSharedMemorySize, ASMEM);

    dim3 tb(32, 8);
    transpose_split_kernel<<<dim3(D_MODEL/32, D_MODEL/32), tb>>>(Wq, D_MODEL, D_MODEL, p_wqh, p_wql);
    transpose_split_kernel<<<dim3(D_MODEL/32, D_MODEL/32), tb>>>(Wk, D_MODEL, D_MODEL, p_wqh + D_MODEL*D_MODEL, p_wql + D_MODEL*D_MODEL);
    transpose_split_kernel<<<dim3(D_MODEL/32, D_MODEL/32), tb>>>(Wv, D_MODEL, D_MODEL, p_wqh + 2*D_MODEL*D_MODEL, p_wql + 2*D_MODEL*D_MODEL);
    transpose_split_kernel<<<dim3(D_FF/32, D_MODEL/32), tb>>>(W1, D_MODEL, D_FF, p_w1h, p_w1l);
    transpose_split_kernel<<<dim3(D_MODEL/32, D_FF/32), tb>>>(W2, D_FF, D_MODEL, p_w2h, p_w2l);

    // 1. LN1 -> bf16 hi/lo
    ln_kernel<<<M_TOTAL, 128>>>(x, g1, be1, p_xh, p_xl);
    // 2. QKV: bf16 hi/lo head-permuted outputs
    mma_gemm_kernel<0><<<dim3(3*D_MODEL/128, M_TOTAL/128), 256, GSMEM>>>(
        p_xh, p_xl, p_wqh, p_wql, D_MODEL, bq, bk, bv, nullptr, nullptr,
        p_qh, p_ql, p_kh, p_kl, p_vh, p_vl);
    // 3. fused sigmoid attention (register S-reuse)
    attn_kernel<<<dim3(SEQ/128, BH), 256, ASMEM>>>(
        p_qh, p_ql, p_kh, p_kl, p_vh, p_vl, p_attn);
    // 4. residual + LN2
    addln_kernel<<<M_TOTAL, 128>>>(x, p_attn, g2, be2, p_x2, p_x2h, p_x2l);
    // 5. FFN1: relu(xn2 @ W1 + b1) -> bf16 hi/lo
    mma_gemm_kernel<1><<<dim3(D_FF/128, M_TOTAL/128), 256, GSMEM>>>(
        p_x2h, p_x2l, p_w1h, p_w1l, D_MODEL, b1, nullptr, nullptr, nullptr, nullptr,
        p_fh, p_fl, nullptr, nullptr, nullptr, nullptr);
    // 6. FFN2: ffh @ W2 + b2 + x2 -> out
    mma_gemm_kernel<2><<<dim3(D_MODEL/128, M_TOTAL/128), 256, GSMEM>>>(
        p_fh, p_fl, p_w2h, p_w2l, D_FF, b2, nullptr, nullptr, p_x2, out,
        nullptr, nullptr, nullptr, nullptr, nullptr, nullptr);
}

// round 10
// speedup vs baseline: 2.5705x; 1.0140x over previous
#include <cuda_runtime.h>
#include <cuda_bf16.h>
#include <cstdint>
#include <math.h>

#define D_MODEL 512
#define N_HEADS 8
#define D_HEAD 64
#define D_FF 2048
#define BATCH 4
#define SEQ 2048
#define M_TOTAL (BATCH * SEQ)   // 8192
#define BH (BATCH * N_HEADS)    // 32

typedef __nv_bfloat16 bf16;

// ---------------- scratch (no cudaMalloc allowed) ----------------
__device__ __align__(16) bf16  g_xh[M_TOTAL * D_MODEL];
__device__ __align__(16) bf16  g_xl[M_TOTAL * D_MODEL];
__device__ __align__(16) bf16  g_qh[M_TOTAL * D_MODEL];
__device__ __align__(16) bf16  g_ql[M_TOTAL * D_MODEL];
__device__ __align__(16) bf16  g_kh[M_TOTAL * D_MODEL];
__device__ __align__(16) bf16  g_kl[M_TOTAL * D_MODEL];
__device__ __align__(16) bf16  g_vh[M_TOTAL * D_MODEL];
__device__ __align__(16) bf16  g_vl[M_TOTAL * D_MODEL];
__device__ __align__(16) float g_attn[M_TOTAL * D_MODEL];
__device__ __align__(16) float g_x2[M_TOTAL * D_MODEL];
__device__ __align__(16) bf16  g_x2h[M_TOTAL * D_MODEL];
__device__ __align__(16) bf16  g_x2l[M_TOTAL * D_MODEL];
__device__ __align__(16) bf16  g_fh[M_TOTAL * D_FF];
__device__ __align__(16) bf16  g_fl[M_TOTAL * D_FF];
__device__ __align__(16) bf16  g_wqh[3 * D_MODEL * D_MODEL];
__device__ __align__(16) bf16  g_wql[3 * D_MODEL * D_MODEL];
__device__ __align__(16) bf16  g_w1h[D_FF * D_MODEL];
__device__ __align__(16) bf16  g_w1l[D_FF * D_MODEL];
__device__ __align__(16) bf16  g_w2h[D_MODEL * D_FF];
__device__ __align__(16) bf16  g_w2l[D_MODEL * D_FF];

// ---------------- helpers ----------------
__device__ __forceinline__ uint32_t smem_u32(const void* p) {
    uint32_t a;
    asm("{ .reg .u64 t; cvta.to.shared.u64 t, %1; cvt.u32.u64 %0, t; }" : "=r"(a) : "l"(p));
    return a;
}
__device__ __forceinline__ void cp16(uint32_t dst, const void* src) {
    asm volatile("cp.async.cg.shared.global [%0], [%1], 16;" :: "r"(dst), "l"(src));
}
#define CP_COMMIT() asm volatile("cp.async.commit_group;" ::: "memory")
#define CP_WAIT0()  asm volatile("cp.async.wait_group 0;" ::: "memory")
#define CP_WAIT1()  asm volatile("cp.async.wait_group 1;" ::: "memory")

__device__ __forceinline__ void ldsm4(uint32_t* r, uint32_t addr) {
    asm volatile("ldmatrix.sync.aligned.m8n8.x4.shared.b16 {%0,%1,%2,%3}, [%4];"
                 : "=r"(r[0]), "=r"(r[1]), "=r"(r[2]), "=r"(r[3]) : "r"(addr));
}
__device__ __forceinline__ void ldsm4t(uint32_t* r, uint32_t addr) {
    asm volatile("ldmatrix.sync.aligned.m8n8.x4.trans.shared.b16 {%0,%1,%2,%3}, [%4];"
                 : "=r"(r[0]), "=r"(r[1]), "=r"(r[2]), "=r"(r[3]) : "r"(addr));
}
__device__ __forceinline__ void mma16816(float* d, const uint32_t* a, uint32_t b0, uint32_t b1) {
    asm volatile(
        "mma.sync.aligned.m16n8k16.row.col.f32.bf16.bf16.f32 "
        "{%0,%1,%2,%3},{%4,%5,%6,%7},{%8,%9},{%0,%1,%2,%3};"
        : "+f"(d[0]), "+f"(d[1]), "+f"(d[2]), "+f"(d[3])
        : "r"(a[0]), "r"(a[1]), "r"(a[2]), "r"(a[3]), "r"(b0), "r"(b1));
}
__device__ __forceinline__ float sigmoid_fast(float xhalf) {
    float t;
    asm("tanh.approx.f32 %0, %1;" : "=f"(t) : "f"(xhalf));
    return fmaf(t, 0.5f, 0.5f);
}
__device__ __forceinline__ void split_pack(float v0, float v1, uint32_t& hp, uint32_t& lp) {
    bf16 h0 = __float2bfloat16(v0), h1 = __float2bfloat16(v1);
    __nv_bfloat162 h2; h2.x = h0; h2.y = h1;
    hp = *(uint32_t*)&h2;
    __nv_bfloat162 l2;
    l2.x = __float2bfloat16(v0 - __bfloat162float(h0));
    l2.y = __float2bfloat16(v1 - __bfloat162float(h1));
    lp = *(uint32_t*)&l2;
}

// ---------------- weight transpose + bf16 split ----------------
__global__ void transpose_split_kernel(const float* __restrict__ W, int K, int N,
                                       bf16* __restrict__ oh, bf16* __restrict__ ol) {
    __shared__ float t[32][33];
    int n0 = blockIdx.x * 32, k0 = blockIdx.y * 32;
    int x = threadIdx.x, y = threadIdx.y;   // 32 x 8
    #pragma unroll
    for (int i = 0; i < 4; i++)
        t[y + 8 * i][x] = W[(size_t)(k0 + y + 8 * i) * N + n0 + x];
    __syncthreads();
    #pragma unroll
    for (int i = 0; i < 4; i++) {
        float v = t[x][y + 8 * i];
        bf16 h = __float2bfloat16(v);
        bf16 l = __float2bfloat16(v - __bfloat162float(h));
        size_t o = (size_t)(n0 + y + 8 * i) * K + k0 + x;
        oh[o] = h; ol[o] = l;
    }
}

// ---------------- LayerNorm -> bf16 hi/lo ----------------
__global__ void ln_kernel(const float* __restrict__ x,
                          const float* __restrict__ g,
                          const float* __restrict__ beta,
                          bf16* __restrict__ oh, bf16* __restrict__ ol) {
    int row = blockIdx.x;
    int t = threadIdx.x;             // 128
    float4 v = ((const float4*)(x + (size_t)row * D_MODEL))[t];
    float s  = v.x + v.y + v.z + v.w;
    float s2 = v.x*v.x + v.y*v.y + v.z*v.z + v.w*v.w;
    #pragma unroll
    for (int o = 16; o; o >>= 1) {
        s  += __shfl_xor_sync(0xffffffffu, s,  o);
        s2 += __shfl_xor_sync(0xffffffffu, s2, o);
    }
    __shared__ float sh[8];
    int w = t >> 5, l = t & 31;
    if (l == 0) { sh[w] = s; sh[4 + w] = s2; }
    __syncthreads();
    s  = sh[0] + sh[1] + sh[2] + sh[3];
    s2 = sh[4] + sh[5] + sh[6] + sh[7];
    float mu  = s * (1.0f / D_MODEL);
    float var = s2 * (1.0f / D_MODEL) - mu * mu;
    float r = rsqrtf(var + 1e-5f);
    float4 gv = ((const float4*)g)[t];
    float4 bv = ((const float4*)beta)[t];
    float o4[4];
    o4[0] = (v.x - mu) * r * gv.x + bv.x;
    o4[1] = (v.y - mu) * r * gv.y + bv.y;
    o4[2] = (v.z - mu) * r * gv.z + bv.z;
    o4[3] = (v.w - mu) * r * gv.w + bv.w;
    size_t base = (size_t)row * D_MODEL + 4 * t;
    #pragma unroll
    for (int i = 0; i < 4; i++) {
        bf16 h = __float2bfloat16(o4[i]);
        oh[base + i] = h;
        ol[base + i] = __float2bfloat16(o4[i] - __bfloat162float(h));
    }
}

__global__ void addln_kernel(const float* __restrict__ x,
                             const float* __restrict__ attn,
                             const float* __restrict__ g,
                             const float* __restrict__ beta,
                             float* __restrict__ x2,
                             bf16* __restrict__ oh, bf16* __restrict__ ol) {
    int row = blockIdx.x;
    int t = threadIdx.x;
    float4 a = ((const float4*)(x + (size_t)row * D_MODEL))[t];
    float4 b = ((const float4*)(attn + (size_t)row * D_MODEL))[t];
    float4 v; v.x = a.x + b.x; v.y = a.y + b.y; v.z = a.z + b.z; v.w = a.w + b.w;
    ((float4*)(x2 + (size_t)row * D_MODEL))[t] = v;
    float s  = v.x + v.y + v.z + v.w;
    float s2 = v.x*v.x + v.y*v.y + v.z*v.z + v.w*v.w;
    #pragma unroll
    for (int o = 16; o; o >>= 1) {
        s  += __shfl_xor_sync(0xffffffffu, s,  o);
        s2 += __shfl_xor_sync(0xffffffffu, s2, o);
    }
    __shared__ float sh[8];
    int w = t >> 5, l = t & 31;
    if (l == 0) { sh[w] = s; sh[4 + w] = s2; }
    __syncthreads();
    s  = sh[0] + sh[1] + sh[2] + sh[3];
    s2 = sh[4] + sh[5] + sh[6] + sh[7];
    float mu  = s * (1.0f / D_MODEL);
    float var = s2 * (1.0f / D_MODEL) - mu * mu;
    float r = rsqrtf(var + 1e-5f);
    float4 gv = ((const float4*)g)[t];
    float4 bv = ((const float4*)beta)[t];
    float o4[4];
    o4[0] = (v.x - mu) * r * gv.x + bv.x;
    o4[1] = (v.y - mu) * r * gv.y + bv.y;
    o4[2] = (v.z - mu) * r * gv.z + bv.z;
    o4[3] = (v.w - mu) * r * gv.w + bv.w;
    size_t base = (size_t)row * D_MODEL + 4 * t;
    #pragma unroll
    for (int i = 0; i < 4; i++) {
        bf16 h = __float2bfloat16(o4[i]);
        oh[base + i] = h;
        ol[base + i] = __float2bfloat16(o4[i] - __bfloat162float(h));
    }
}

// ---------------- mma.sync GEMM: 512 threads, warp tile 32x32 ----------------
// CTA tile 128x128, 16 warps (4x4), K-chunk 32, 2-stage cp.async.
// Per-thread acc shrinks 64->32 regs so 16 warps fit one SM (4 warps/SMSP).
#define GCH   (128 * 48)
#define GMAT  (2 * GCH)
#define GSTAGE (4 * GMAT)
#define GSMEM (2 * GSTAGE)

template <int MODE>
__global__ void __launch_bounds__(512) mma_gemm_kernel(
    const bf16* __restrict__ Ahi, const bf16* __restrict__ Alo,
    const bf16* __restrict__ Bhi, const bf16* __restrict__ Blo,
    int Kdim,
    const float* __restrict__ b0, const float* __restrict__ b1, const float* __restrict__ b2,
    const float* __restrict__ res,
    float* __restrict__ o32,
    bf16* __restrict__ oh0, bf16* __restrict__ ol0,
    bf16* __restrict__ oh1, bf16* __restrict__ ol1,
    bf16* __restrict__ oh2, bf16* __restrict__ ol2)
{
    extern __shared__ char smem[];
    uint32_t sb = smem_u32(smem);
    int tid = threadIdx.x, wid = tid >> 5, lane = tid & 31;
    int wr = wid >> 2, wc = wid & 3;     // 4x4 warp grid, each 32x32
    int m0 = blockIdx.y * 128, n0 = blockIdx.x * 128;
    const bf16* srcs[4] = {Ahi, Alo, Bhi, Blo};

    auto load_stage = [&](int c, int s) {
        #pragma unroll
        for (int i = 0; i < 4; i++) {
            int idx = i * 512 + tid;
            int mat = idx >> 9;
            int rem = idx & 511;
            int row = rem >> 2;
            int q = rem & 3, kk = q >> 1, half = q & 1;
            const bf16* src = srcs[mat] +
                (size_t)(((mat < 2) ? m0 : n0) + row) * Kdim + c * 32 + kk * 16 + half * 8;
            uint32_t dst = sb + s * GSTAGE + mat * GMAT + kk * GCH + row * 48 + half * 16;
            cp16(dst, src);
        }
    };

    float acc[2][4][4];
    #pragma unroll
    for (int a = 0; a < 2; a++)
        #pragma unroll
        for (int b = 0; b < 4; b++)
            #pragma unroll
            for (int cc = 0; cc < 4; cc++) acc[a][b][cc] = 0.f;

    load_stage(0, 0);
    CP_COMMIT();

    int arow = lane & 15, ahalf = lane >> 4;
    int brow = (lane & 7) + ((lane >> 4) << 3), bhalf = (lane >> 3) & 1;
    int nc = Kdim >> 5;
    for (int c = 0; c < nc; c++) {
        int s = c & 1;
        if (c + 1 < nc) { load_stage(c + 1, s ^ 1); CP_COMMIT(); CP_WAIT1(); }
        else CP_WAIT0();
        __syncthreads();

        #pragma unroll
        for (int kk = 0; kk < 2; kk++) {
            uint32_t abase = sb + s * GSTAGE + kk * GCH;
            uint32_t ah[2][4], al[2][4];
            #pragma unroll
            for (int mt = 0; mt < 2; mt++) {
                uint32_t ad = abase + (uint32_t)(wr * 32 + mt * 16 + arow) * 48 + ahalf * 16;
                ldsm4(ah[mt], ad);
                ldsm4(al[mt], ad + GMAT);
            }
            uint32_t bh[2][4], bl[2][4];
            #pragma unroll
            for (int p = 0; p < 2; p++) {
                uint32_t bd = sb + s * GSTAGE + 2 * GMAT + kk * GCH +
                              (uint32_t)(wc * 32 + p * 16 + brow) * 48 + bhalf * 16;
                ldsm4(bh[p], bd);
                ldsm4(bl[p], bd + GMAT);
            }
            #pragma unroll
            for (int mt = 0; mt < 2; mt++)
                #pragma unroll
                for (int nt = 0; nt < 4; nt++) {
                    uint32_t hb0 = bh[nt >> 1][(nt & 1) * 2], hb1 = bh[nt >> 1][(nt & 1) * 2 + 1];
                    uint32_t lb0 = bl[nt >> 1][(nt & 1) * 2], lb1 = bl[nt >> 1][(nt & 1) * 2 + 1];
                    mma16816(acc[mt][nt], ah[mt], hb0, hb1);
                    mma16816(acc[mt][nt], ah[mt], lb0, lb1);
                    mma16816(acc[mt][nt], al[mt], hb0, hb1);
                }
        }
        __syncthreads();
    }

    #pragma unroll
    for (int mt = 0; mt < 2; mt++) {
        int r0 = m0 + wr * 32 + mt * 16 + (lane >> 2);
        #pragma unroll
        for (int nt = 0; nt < 4; nt++) {
            int nglob = n0 + wc * 32 + nt * 8 + (lane & 3) * 2;
            if (MODE == 0) {
                int z = nglob >> 9;
                int nn = nglob & 511;
                int h = nn >> 6, dh = nn & 63;
                const float* bias = (z == 0) ? b0 : (z == 1) ? b1 : b2;
                bf16* OH = (z == 0) ? oh0 : (z == 1) ? oh1 : oh2;
                bf16* OL = (z == 0) ? ol0 : (z == 1) ? ol1 : ol2;
                float bv0 = bias[nn], bv1 = bias[nn + 1];
                #pragma unroll
                for (int j = 0; j < 2; j++) {
                    int r = r0 + j * 8;
                    int bb = r >> 11, sidx = r & 2047;
                    size_t dst = ((size_t)((bb * N_HEADS + h) * SEQ + sidx)) * D_HEAD + dh;
                    float v0 = acc[mt][nt][2 * j] + bv0;
                    float v1 = acc[mt][nt][2 * j + 1] + bv1;
                    uint32_t hp, lp;
                    split_pack(v0, v1, hp, lp);
                    *(uint32_t*)(OH + dst) = hp;
                    *(uint32_t*)(OL + dst) = lp;
                }
            } else if (MODE == 1) {
                float bv0 = b0[nglob], bv1 = b0[nglob + 1];
                #pragma unroll
                for (int j = 0; j < 2; j++) {
                    int r = r0 + j * 8;
                    size_t dst = (size_t)r * D_FF + nglob;
                    float v0 = fmaxf(acc[mt][nt][2 * j] + bv0, 0.f);
                    float v1 = fmaxf(acc[mt][nt][2 * j + 1] + bv1, 0.f);
                    uint32_t hp, lp;
                    split_pack(v0, v1, hp, lp);
                    *(uint32_t*)(oh0 + dst) = hp;
                    *(uint32_t*)(ol0 + dst) = lp;
                }
            } else {
                float bv0 = b0[nglob], bv1 = b0[nglob + 1];
                #pragma unroll
                for (int j = 0; j < 2; j++) {
                    int r = r0 + j * 8;
                    size_t dst = (size_t)r * D_MODEL + nglob;
                    float2 rv = *(const float2*)(res + dst);
                    float2 ov;
                    ov.x = acc[mt][nt][2 * j] + bv0 + rv.x;
                    ov.y = acc[mt][nt][2 * j + 1] + bv1 + rv.y;
                    *(float2*)(o32 + dst) = ov;
                }
            }
        }
    }
}

// ---------------- fused sigmoid attention: register S-reuse (unchanged) ----------------
#define AKCH  (64 * 48)
#define AKMAT (4 * AKCH)
#define AKSTG (4 * AKMAT)
#define AQOFF (2 * AKSTG)
#define AQCH  (128 * 48)
#define AQMAT (4 * AQCH)
#define ASMEM (AQOFF + 2 * AQMAT)    // 147456
#define ATT_HSCALE 0.022097086912079608f

__global__ void __launch_bounds__(256) attn_kernel(
    const bf16* __restrict__ Qh, const bf16* __restrict__ Ql,
    const bf16* __restrict__ Kh, const bf16* __restrict__ Kl,
    const bf16* __restrict__ Vh, const bf16* __restrict__ Vl,
    float* __restrict__ O)
{
    extern __shared__ char smem[];
    uint32_t sb = smem_u32(smem);
    int tid = threadIdx.x, wid = tid >> 5, lane = tid & 31;
    int wq = wid >> 1, wk = wid & 1;
    int bh = blockIdx.y;
    int q0 = blockIdx.x * 128;
    size_t bhbase = (size_t)bh * SEQ * D_HEAD;

    {
        const bf16* qs[2] = {Qh, Ql};
        #pragma unroll
        for (int i = 0; i < 8; i++) {
            int idx = i * 256 + tid;
            int mat = idx >> 10;
            int rem = idx & 1023;
            int row = rem >> 3;
            int q = rem & 7, cc = q >> 1, half = q & 1;
            const bf16* src = qs[mat] + bhbase + (size_t)(q0 + row) * D_HEAD + cc * 16 + half * 8;
            uint32_t dst = sb + AQOFF + mat * AQMAT + cc * AQCH + row * 48 + half * 16;
            cp16(dst, src);
        }
    }

    const bf16* kvs[4] = {Kh, Kl, Vh, Vl};
    auto load_kv = [&](int t0, int s) {
        #pragma unroll
        for (int i = 0; i < 8; i++) {
            int idx = i * 256 + tid;
            int mat = idx >> 9;
            int rem = idx & 511;
            int row = rem >> 3;
            int q = rem & 7, cc = q >> 1, half = q & 1;
            const bf16* src = kvs[mat] + bhbase + (size_t)(t0 + row) * D_HEAD + cc * 16 + half * 8;
            uint32_t dst = sb + s * AKSTG + mat * AKMAT + cc * AKCH + row * 48 + half * 16;
            cp16(dst, src);
        }
    };

    load_kv(0, 0);
    CP_COMMIT();

    float oacc[2][8][4];
    #pragma unroll
    for (int a = 0; a < 2; a++)
        #pragma unroll
        for (int b = 0; b < 8; b++)
            #pragma unroll
            for (int cc = 0; cc < 4; cc++) oacc[a][b][cc] = 0.f;

    int arow = lane & 15, ahalf = lane >> 4;
    int brow = (lane & 7) + ((lane >> 4) << 3), bhalf = (lane >> 3) & 1;
    const int niter = SEQ / 64;
    for (int c = 0; c < niter; c++) {
        int s = c & 1;
        if (c + 1 < niter) { load_kv((c + 1) * 64, s ^ 1); CP_COMMIT(); CP_WAIT1(); }
        else CP_WAIT0();
        __syncthreads();

        float sacc[2][4][4];
        #pragma unroll
        for (int a = 0; a < 2; a++)
            #pragma unroll
            for (int b = 0; b < 4; b++)
                #pragma unroll
                for (int cc = 0; cc < 4; cc++) sacc[a][b][cc] = 0.f;

        #pragma unroll
        for (int cc = 0; cc < 4; cc++) {
            uint32_t qah[2][4], qal[2][4];
            #pragma unroll
            for (int mt = 0; mt < 2; mt++) {
                uint32_t ad = sb + AQOFF + cc * AQCH +
                              (uint32_t)(wq * 32 + mt * 16 + arow) * 48 + ahalf * 16;
                ldsm4(qah[mt], ad);
                ldsm4(qal[mt], ad + AQMAT);
            }
            uint32_t kbh[2][4], kbl[2][4];
            #pragma unroll
            for (int p = 0; p < 2; p++) {
                uint32_t bd = sb + s * AKSTG + cc * AKCH +
                              (uint32_t)(wk * 32 + p * 16 + brow) * 48 + bhalf * 16;
                ldsm4(kbh[p], bd);
                ldsm4(kbl[p], bd + AKMAT);
            }
            #pragma unroll
            for (int mt = 0; mt < 2; mt++)
                #pragma unroll
                for (int nt = 0; nt < 4; nt++) {
                    int p = nt >> 1, i0 = (nt & 1) * 2;
                    mma16816(sacc[mt][nt], qah[mt], kbh[p][i0], kbh[p][i0 + 1]);
                    mma16816(sacc[mt][nt], qah[mt], kbl[p][i0], kbl[p][i0 + 1]);
                    mma16816(sacc[mt][nt], qal[mt], kbh[p][i0], kbh[p][i0 + 1]);
                }
        }

        #pragma unroll
        for (int mt = 0; mt < 2; mt++)
            #pragma unroll
            for (int nt = 0; nt < 4; nt++)
                #pragma unroll
                for (int i = 0; i < 4; i++)
                    sacc[mt][nt][i] = sigmoid_fast(sacc[mt][nt][i] * ATT_HSCALE);

        // A-frag order: a0=(row,k0-7), a1=(row+8,k0-7), a2=(row,k8-15), a3=(row+8,k8-15)
        uint32_t Sh[2][2][4], Sl[2][2][4];
        #pragma unroll
        for (int mt = 0; mt < 2; mt++)
            #pragma unroll
            for (int kc = 0; kc < 2; kc++) {
                split_pack(sacc[mt][2*kc][0],   sacc[mt][2*kc][1],   Sh[mt][kc][0], Sl[mt][kc][0]);
                split_pack(sacc[mt][2*kc][2],   sacc[mt][2*kc][3],   Sh[mt][kc][1], Sl[mt][kc][1]);
                split_pack(sacc[mt][2*kc+1][0], sacc[mt][2*kc+1][1], Sh[mt][kc][2], Sl[mt][kc][2]);
                split_pack(sacc[mt][2*kc+1][2], sacc[mt][2*kc+1][3], Sh[mt][kc][3], Sl[mt][kc][3]);
            }

        #pragma unroll
        for (int kc = 0; kc < 2; kc++) {
            #pragma unroll
            for (int dg = 0; dg < 4; dg++) {
                uint32_t vbh[4], vbl[4];
                uint32_t vad = sb + s * AKSTG + 2 * AKMAT + dg * AKCH +
                               (uint32_t)(wk * 32 + kc * 16 + (lane & 15)) * 48 + (lane >> 4) * 16;
                ldsm4t(vbh, vad);
                ldsm4t(vbl, vad + AKMAT);
                #pragma unroll
                for (int mt = 0; mt < 2; mt++)
                    #pragma unroll
                    for (int nt2 = 0; nt2 < 2; nt2++) {
                        float* o = oacc[mt][dg * 2 + nt2];
                        mma16816(o, Sh[mt][kc], vbh[nt2 * 2], vbh[nt2 * 2 + 1]);
                        mma16816(o, Sh[mt][kc], vbl[nt2 * 2], vbl[nt2 * 2 + 1]);
                        mma16816(o, Sl[mt][kc], vbh[nt2 * 2], vbh[nt2 * 2 + 1]);
                    }
            }
        }
        __syncthreads();
    }

    if (wk == 1) {
        #pragma unroll
        for (int mt = 0; mt < 2; mt++)
            #pragma unroll
            for (int nt = 0; nt < 8; nt++)
                #pragma unroll
                for (int j = 0; j < 2; j++) {
                    int r = mt * 16 + (lane >> 2) + j * 8;
                    int col = nt * 8 + (lane & 3) * 2;
                    float2 p; p.x = oacc[mt][nt][2 * j]; p.y = oacc[mt][nt][2 * j + 1];
                    *(float2*)(smem + wq * 8192 + r * 256 + col * 4) = p;
                }
    }
    __syncthreads();
    if (wk == 0) {
        int b = bh >> 3, h = bh & 7;
        #pragma unroll
        for (int mt = 0; mt < 2; mt++)
            #pragma unroll
            for (int nt = 0; nt < 8; nt++)
                #pragma unroll
                for (int j = 0; j < 2; j++) {
                    int r = mt * 16 + (lane >> 2) + j * 8;
                    int col = nt * 8 + (lane & 3) * 2;
                    float2 p = *(const float2*)(smem + wq * 8192 + r * 256 + col * 4);
                    float2 o;
                    o.x = oacc[mt][nt][2 * j] + p.x;
                    o.y = oacc[mt][nt][2 * j + 1] + p.y;
                    *(float2*)(O + (size_t)(b * SEQ + q0 + wq * 32 + r) * D_MODEL + h * D_HEAD + col) = o;
                }
    }
}

// ---------------- launch ----------------
extern "C" void kernel_launch(void* const* d_in, const int* in_sizes, int n_in,
                              void* d_out, int out_size) {
    const float* x   = (const float*)d_in[0];
    const float* Wq  = (const float*)d_in[1];
    const float* bq  = (const float*)d_in[2];
    const float* Wk  = (const float*)d_in[3];
    const float* bk  = (const float*)d_in[4];
    const float* Wv  = (const float*)d_in[5];
    const float* bv  = (const float*)d_in[6];
    const float* W1  = (const float*)d_in[7];
    const float* b1  = (const float*)d_in[8];
    const float* W2  = (const float*)d_in[9];
    const float* b2  = (const float*)d_in[10];
    const float* g1  = (const float*)d_in[11];
    const float* be1 = (const float*)d_in[12];
    const float* g2  = (const float*)d_in[13];
    const float* be2 = (const float*)d_in[14];
    float* out = (float*)d_out;

    bf16 *p_xh, *p_xl, *p_x2h, *p_x2l, *p_fh, *p_fl;
    bf16 *p_qh, *p_ql, *p_kh, *p_kl, *p_vh, *p_vl;
    bf16 *p_wqh, *p_wql, *p_w1h, *p_w1l, *p_w2h, *p_w2l;
    float *p_attn, *p_x2;
    cudaGetSymbolAddress((void**)&p_xh, g_xh);
    cudaGetSymbolAddress((void**)&p_xl, g_xl);
    cudaGetSymbolAddress((void**)&p_qh, g_qh);
    cudaGetSymbolAddress((void**)&p_ql, g_ql);
    cudaGetSymbolAddress((void**)&p_kh, g_kh);
    cudaGetSymbolAddress((void**)&p_kl, g_kl);
    cudaGetSymbolAddress((void**)&p_vh, g_vh);
    cudaGetSymbolAddress((void**)&p_vl, g_vl);
    cudaGetSymbolAddress((void**)&p_attn, g_attn);
    cudaGetSymbolAddress((void**)&p_x2, g_x2);
    cudaGetSymbolAddress((void**)&p_x2h, g_x2h);
    cudaGetSymbolAddress((void**)&p_x2l, g_x2l);
    cudaGetSymbolAddress((void**)&p_fh, g_fh);
    cudaGetSymbolAddress((void**)&p_fl, g_fl);
    cudaGetSymbolAddress((void**)&p_wqh, g_wqh);
    cudaGetSymbolAddress((void**)&p_wql, g_wql);
    cudaGetSymbolAddress((void**)&p_w1h, g_w1h);
    cudaGetSymbolAddress((void**)&p_w1l, g_w1l);
    cudaGetSymbolAddress((void**)&p_w2h, g_w2h);
    cudaGetSymbolAddress((void**)&p_w2l, g_w2l);

    cudaFuncSetAttribute(mma_gemm_kernel<0>, cudaFuncAttributeMaxDynamicSharedMemorySize, GSMEM);
    cudaFuncSetAttribute(mma_gemm_kernel<1>, cudaFuncAttributeMaxDynamicSharedMemorySize, GSMEM);
    cudaFuncSetAttribute(mma_gemm_kernel<2>, cudaFuncAttributeMaxDynamicSharedMemorySize, GSMEM);
    cudaFuncSetAttribute(attn_kernel, cudaFuncAttributeMaxDynamicSharedMemorySize, ASMEM);

    dim3 tb(32, 8);
    transpose_split_kernel<<<dim3(D_MODEL/32, D_MODEL/32), tb>>>(Wq, D_MODEL, D_MODEL, p_wqh, p_wql);
    transpose_split_kernel<<<dim3(D_MODEL/32, D_MODEL/32), tb>>>(Wk, D_MODEL, D_MODEL, p_wqh + D_MODEL*D_MODEL, p_wql + D_MODEL*D_MODEL);
    transpose_split_kernel<<<dim3(D_MODEL/32, D_MODEL/32), tb>>>(Wv, D_MODEL, D_MODEL, p_wqh + 2*D_MODEL*D_MODEL, p_wql + 2*D_MODEL*D_MODEL);
    transpose_split_kernel<<<dim3(D_FF/32, D_MODEL/32), tb>>>(W1, D_MODEL, D_FF, p_w1h, p_w1l);
    transpose_split_kernel<<<dim3(D_MODEL/32, D_FF/32), tb>>>(W2, D_FF, D_MODEL, p_w2h, p_w2l);

    // 1. LN1 -> bf16 hi/lo
    ln_kernel<<<M_TOTAL, 128>>>(x, g1, be1, p_xh, p_xl);
    // 2. QKV: bf16 hi/lo head-permuted outputs
    mma_gemm_kernel<0><<<dim3(3*D_MODEL/128, M_TOTAL/128), 512, GSMEM>>>(
        p_xh, p_xl, p_wqh, p_wql, D_MODEL, bq, bk, bv, nullptr, nullptr,
        p_qh, p_ql, p_kh, p_kl, p_vh, p_vl);
    // 3. fused sigmoid attention (register S-reuse)
    attn_kernel<<<dim3(SEQ/128, BH), 256, ASMEM>>>(
        p_qh, p_ql, p_kh, p_kl, p_vh, p_vl, p_attn);
    // 4. residual + LN2
    addln_kernel<<<M_TOTAL, 128>>>(x, p_attn, g2, be2, p_x2, p_x2h, p_x2l);
    // 5. FFN1: relu(xn2 @ W1 + b1) -> bf16 hi/lo
    mma_gemm_kernel<1><<<dim3(D_FF/128, M_TOTAL/128), 512, GSMEM>>>(
        p_x2h, p_x2l, p_w1h, p_w1l, D_MODEL, b1, nullptr, nullptr, nullptr, nullptr,
        p_fh, p_fl, nullptr, nullptr, nullptr, nullptr);
    // 6. FFN2: ffh @ W2 + b2 + x2 -> out
    mma_gemm_kernel<2><<<dim3(D_MODEL/128, M_TOTAL/128), 512, GSMEM>>>(
        p_fh, p_fl, p_w2h, p_w2l, D_FF, b2, nullptr, nullptr, p_x2, out,
        nullptr, nullptr, nullptr, nullptr, nullptr, nullptr);
}

// round 13
// speedup vs baseline: 2.6662x; 1.0372x over previous
#include <cuda_runtime.h>
#include <cuda_bf16.h>
#include <cstdint>
#include <math.h>

#define D_MODEL 512
#define N_HEADS 8
#define D_HEAD 64
#define D_FF 2048
#define BATCH 4
#define SEQ 2048
#define M_TOTAL (BATCH * SEQ)   // 8192
#define BH (BATCH * N_HEADS)    // 32

typedef __nv_bfloat16 bf16;

// ---------------- scratch (no cudaMalloc allowed) ----------------
__device__ __align__(16) bf16  g_xh[M_TOTAL * D_MODEL];
__device__ __align__(16) bf16  g_xl[M_TOTAL * D_MODEL];
__device__ __align__(16) bf16  g_qh[M_TOTAL * D_MODEL];
__device__ __align__(16) bf16  g_ql[M_TOTAL * D_MODEL];
__device__ __align__(16) bf16  g_kh[M_TOTAL * D_MODEL];
__device__ __align__(16) bf16  g_kl[M_TOTAL * D_MODEL];
__device__ __align__(16) bf16  g_vh[M_TOTAL * D_MODEL];
__device__ __align__(16) bf16  g_vl[M_TOTAL * D_MODEL];
__device__ __align__(16) float g_attn[M_TOTAL * D_MODEL];
__device__ __align__(16) float g_x2[M_TOTAL * D_MODEL];
__device__ __align__(16) bf16  g_x2h[M_TOTAL * D_MODEL];
__device__ __align__(16) bf16  g_x2l[M_TOTAL * D_MODEL];
__device__ __align__(16) bf16  g_fh[M_TOTAL * D_FF];
__device__ __align__(16) bf16  g_fl[M_TOTAL * D_FF];
__device__ __align__(16) bf16  g_wqh[3 * D_MODEL * D_MODEL];
__device__ __align__(16) bf16  g_wql[3 * D_MODEL * D_MODEL];
__device__ __align__(16) bf16  g_w1h[D_FF * D_MODEL];
__device__ __align__(16) bf16  g_w1l[D_FF * D_MODEL];
__device__ __align__(16) bf16  g_w2h[D_MODEL * D_FF];
__device__ __align__(16) bf16  g_w2l[D_MODEL * D_FF];

// ---------------- helpers ----------------
__device__ __forceinline__ uint32_t smem_u32(const void* p) {
    uint32_t a;
    asm("{ .reg .u64 t; cvta.to.shared.u64 t, %1; cvt.u32.u64 %0, t; }" : "=r"(a) : "l"(p));
    return a;
}
__device__ __forceinline__ void cp16(uint32_t dst, const void* src) {
    asm volatile("cp.async.cg.shared.global [%0], [%1], 16;" :: "r"(dst), "l"(src));
}
#define CP_COMMIT() asm volatile("cp.async.commit_group;" ::: "memory")
#define CP_WAIT0()  asm volatile("cp.async.wait_group 0;" ::: "memory")
#define CP_WAIT1()  asm volatile("cp.async.wait_group 1;" ::: "memory")

__device__ __forceinline__ void ldsm4(uint32_t* r, uint32_t addr) {
    asm volatile("ldmatrix.sync.aligned.m8n8.x4.shared.b16 {%0,%1,%2,%3}, [%4];"
                 : "=r"(r[0]), "=r"(r[1]), "=r"(r[2]), "=r"(r[3]) : "r"(addr));
}
__device__ __forceinline__ void ldsm4t(uint32_t* r, uint32_t addr) {
    asm volatile("ldmatrix.sync.aligned.m8n8.x4.trans.shared.b16 {%0,%1,%2,%3}, [%4];"
                 : "=r"(r[0]), "=r"(r[1]), "=r"(r[2]), "=r"(r[3]) : "r"(addr));
}
__device__ __forceinline__ void mma16816(float* d, const uint32_t* a, uint32_t b0, uint32_t b1) {
    asm volatile(
        "mma.sync.aligned.m16n8k16.row.col.f32.bf16.bf16.f32 "
        "{%0,%1,%2,%3},{%4,%5,%6,%7},{%8,%9},{%0,%1,%2,%3};"
        : "+f"(d[0]), "+f"(d[1]), "+f"(d[2]), "+f"(d[3])
        : "r"(a[0]), "r"(a[1]), "r"(a[2]), "r"(a[3]), "r"(b0), "r"(b1));
}
__device__ __forceinline__ float sigmoid_fast(float xhalf) {
    float t;
    asm("tanh.approx.f32 %0, %1;" : "=f"(t) : "f"(xhalf));
    return fmaf(t, 0.5f, 0.5f);
}
__device__ __forceinline__ void split_pack(float v0, float v1, uint32_t& hp, uint32_t& lp) {
    bf16 h0 = __float2bfloat16(v0), h1 = __float2bfloat16(v1);
    __nv_bfloat162 h2; h2.x = h0; h2.y = h1;
    hp = *(uint32_t*)&h2;
    __nv_bfloat162 l2;
    l2.x = __float2bfloat16(v0 - __bfloat162float(h0));
    l2.y = __float2bfloat16(v1 - __bfloat162float(h1));
    lp = *(uint32_t*)&l2;
}

// ---------------- fused weight transpose + bf16 split (ALL 5 weights) ----------------
// block = 32x8. 2816 blocks: [0,768) Wq/Wk/Wv (16x16 each), [768,1792) W1, [1792,2816) W2.
__global__ void transpose_split_all_kernel(
    const float* __restrict__ Wq, const float* __restrict__ Wk, const float* __restrict__ Wv,
    const float* __restrict__ W1, const float* __restrict__ W2,
    bf16* __restrict__ wqh, bf16* __restrict__ wql,
    bf16* __restrict__ w1h, bf16* __restrict__ w1l,
    bf16* __restrict__ w2h, bf16* __restrict__ w2l)
{
    int bid = blockIdx.x;
    const float* W; bf16 *oh, *ol; int K, N, n0, k0;
    if (bid < 768) {
        int idx = bid / 256, rem = bid % 256;
        W = (idx == 0) ? Wq : (idx == 1) ? Wk : Wv;
        oh = wqh + idx * D_MODEL * D_MODEL;
        ol = wql + idx * D_MODEL * D_MODEL;
        K = D_MODEL; N = D_MODEL;
        n0 = (rem & 15) * 32; k0 = (rem >> 4) * 32;
    } else if (bid < 1792) {
        int rem = bid - 768;
        W = W1; oh = w1h; ol = w1l;
        K = D_MODEL; N = D_FF;
        n0 = (rem & 63) * 32; k0 = (rem >> 6) * 32;
    } else {
        int rem = bid - 1792;
        W = W2; oh = w2h; ol = w2l;
        K = D_FF; N = D_MODEL;
        n0 = (rem & 15) * 32; k0 = (rem >> 4) * 32;
    }
    __shared__ float t[32][33];
    int x = threadIdx.x, y = threadIdx.y;
    #pragma unroll
    for (int i = 0; i < 4; i++)
        t[y + 8 * i][x] = W[(size_t)(k0 + y + 8 * i) * N + n0 + x];
    __syncthreads();
    #pragma unroll
    for (int i = 0; i < 4; i++) {
        float v = t[x][y + 8 * i];
        bf16 h = __float2bfloat16(v);
        bf16 l = __float2bfloat16(v - __bfloat162float(h));
        size_t o = (size_t)(n0 + y + 8 * i) * K + k0 + x;
        oh[o] = h; ol[o] = l;
    }
}

// ---------------- LayerNorm -> bf16 hi/lo ----------------
__global__ void ln_kernel(const float* __restrict__ x,
                          const float* __restrict__ g,
                          const float* __restrict__ beta,
                          bf16* __restrict__ oh, bf16* __restrict__ ol) {
    int row = blockIdx.x;
    int t = threadIdx.x;             // 128
    float4 v = ((const float4*)(x + (size_t)row * D_MODEL))[t];
    float s  = v.x + v.y + v.z + v.w;
    float s2 = v.x*v.x + v.y*v.y + v.z*v.z + v.w*v.w;
    #pragma unroll
    for (int o = 16; o; o >>= 1) {
        s  += __shfl_xor_sync(0xffffffffu, s,  o);
        s2 += __shfl_xor_sync(0xffffffffu, s2, o);
    }
    __shared__ float sh[8];
    int w = t >> 5, l = t & 31;
    if (l == 0) { sh[w] = s; sh[4 + w] = s2; }
    __syncthreads();
    s  = sh[0] + sh[1] + sh[2] + sh[3];
    s2 = sh[4] + sh[5] + sh[6] + sh[7];
    float mu  = s * (1.0f / D_MODEL);
    float var = s2 * (1.0f / D_MODEL) - mu * mu;
    float r = rsqrtf(var + 1e-5f);
    float4 gv = ((const float4*)g)[t];
    float4 bv = ((const float4*)beta)[t];
    float o4[4];
    o4[0] = (v.x - mu) * r * gv.x + bv.x;
    o4[1] = (v.y - mu) * r * gv.y + bv.y;
    o4[2] = (v.z - mu) * r * gv.z + bv.z;
    o4[3] = (v.w - mu) * r * gv.w + bv.w;
    size_t base = (size_t)row * D_MODEL + 4 * t;
    #pragma unroll
    for (int i = 0; i < 4; i++) {
        bf16 h = __float2bfloat16(o4[i]);
        oh[base + i] = h;
        ol[base + i] = __float2bfloat16(o4[i] - __bfloat162float(h));
    }
}

__global__ void addln_kernel(const float* __restrict__ x,
                             const float* __restrict__ attn,
                             const float* __restrict__ g,
                             const float* __restrict__ beta,
                             float* __restrict__ x2,
                             bf16* __restrict__ oh, bf16* __restrict__ ol) {
    int row = blockIdx.x;
    int t = threadIdx.x;
    float4 a = ((const float4*)(x + (size_t)row * D_MODEL))[t];
    float4 b = ((const float4*)(attn + (size_t)row * D_MODEL))[t];
    float4 v; v.x = a.x + b.x; v.y = a.y + b.y; v.z = a.z + b.z; v.w = a.w + b.w;
    ((float4*)(x2 + (size_t)row * D_MODEL))[t] = v;
    float s  = v.x + v.y + v.z + v.w;
    float s2 = v.x*v.x + v.y*v.y + v.z*v.z + v.w*v.w;
    #pragma unroll
    for (int o = 16; o; o >>= 1) {
        s  += __shfl_xor_sync(0xffffffffu, s,  o);
        s2 += __shfl_xor_sync(0xffffffffu, s2, o);
    }
    __shared__ float sh[8];
    int w = t >> 5, l = t & 31;
    if (l == 0) { sh[w] = s; sh[4 + w] = s2; }
    __syncthreads();
    s  = sh[0] + sh[1] + sh[2] + sh[3];
    s2 = sh[4] + sh[5] + sh[6] + sh[7];
    float mu  = s * (1.0f / D_MODEL);
    float var = s2 * (1.0f / D_MODEL) - mu * mu;
    float r = rsqrtf(var + 1e-5f);
    float4 gv = ((const float4*)g)[t];
    float4 bv = ((const float4*)beta)[t];
    float o4[4];
    o4[0] = (v.x - mu) * r * gv.x + bv.x;
    o4[1] = (v.y - mu) * r * gv.y + bv.y;
    o4[2] = (v.z - mu) * r * gv.z + bv.z;
    o4[3] = (v.w - mu) * r * gv.w + bv.w;
    size_t base = (size_t)row * D_MODEL + 4 * t;
    #pragma unroll
    for (int i = 0; i < 4; i++) {
        bf16 h = __float2bfloat16(o4[i]);
        oh[base + i] = h;
        ol[base + i] = __float2bfloat16(o4[i] - __bfloat162float(h));
    }
}

// ---------------- mma.sync GEMM: CTA 128x256, 8 warps, warp tile 64x64 ----------------
// Halves LDSM traffic per HMMA vs 128x128 tiling (A amp 4x, B amp 2x, 2x MMAs).
// smem per stage: A hi/lo (128x32) 24576 + B hi/lo (256x32) 49152 = 73728; x2 stages.
#define GA_CH  (128 * 48)            // 6144: A k16 chunk
#define GB_CH  (256 * 48)            // 12288: B k16 chunk
#define GST    73728                 // stage stride
#define GA_HL  12288                 // A mat (2 chunks)
#define GB_HL  24576                 // B mat
#define GSMEM  (2 * GST)             // 147456

template <int MODE>
__global__ void __launch_bounds__(256) mma_gemm_kernel(
    const bf16* __restrict__ Ahi, const bf16* __restrict__ Alo,
    const bf16* __restrict__ Bhi, const bf16* __restrict__ Blo,
    int Kdim,
    const float* __restrict__ b0, const float* __restrict__ b1, const float* __restrict__ b2,
    const float* __restrict__ res,
    float* __restrict__ o32,
    bf16* __restrict__ oh0, bf16* __restrict__ ol0,
    bf16* __restrict__ oh1, bf16* __restrict__ ol1,
    bf16* __restrict__ oh2, bf16* __restrict__ ol2)
{
    extern __shared__ char smem[];
    uint32_t sb = smem_u32(smem);
    int tid = threadIdx.x, wid = tid >> 5, lane = tid & 31;
    int wr = wid >> 2, wc = wid & 3;     // 2x4 warp grid, each 64x64
    int m0 = blockIdx.y * 128, n0 = blockIdx.x * 256;
    const bf16* Asrc[2] = {Ahi, Alo};
    const bf16* Bsrc[2] = {Bhi, Blo};

    // 3072 cp16 per stage: A 1024 (2 mats x 512), B 2048 (2 mats x 1024)
    auto load_stage = [&](int c, int s) {
        #pragma unroll
        for (int i = 0; i < 12; i++) {
            int idx = i * 256 + tid;
            uint32_t dst; const bf16* src;
            if (idx < 1024) {
                int mat = idx >> 9, rem = idx & 511;
                int row = rem >> 2, q = rem & 3, kk = q >> 1, half = q & 1;
                src = Asrc[mat] + (size_t)(m0 + row) * Kdim + c * 32 + kk * 16 + half * 8;
                dst = sb + s * GST + mat * GA_HL + kk * GA_CH + row * 48 + half * 16;
            } else {
                int j = idx - 1024;
                int mat = j >> 10, rem = j & 1023;
                int row = rem >> 2, q = rem & 3, kk = q >> 1, half = q & 1;
                src = Bsrc[mat] + (size_t)(n0 + row) * Kdim + c * 32 + kk * 16 + half * 8;
                dst = sb + s * GST + 2 * GA_HL + mat * GB_HL + kk * GB_CH + row * 48 + half * 16;
            }
            cp16(dst, src);
        }
    };

    float acc[4][8][4];
    #pragma unroll
    for (int a = 0; a < 4; a++)
        #pragma unroll
        for (int b = 0; b < 8; b++)
            #pragma unroll
            for (int cc = 0; cc < 4; cc++) acc[a][b][cc] = 0.f;

    load_stage(0, 0);
    CP_COMMIT();

    int arow = lane & 15, ahalf = lane >> 4;
    int brow = (lane & 7) + ((lane >> 4) << 3), bhalf = (lane >> 3) & 1;
    int nc = Kdim >> 5;
    for (int c = 0; c < nc; c++) {
        int s = c & 1;
        if (c + 1 < nc) { load_stage(c + 1, s ^ 1); CP_COMMIT(); CP_WAIT1(); }
        else CP_WAIT0();
        __syncthreads();

        #pragma unroll
        for (int kk = 0; kk < 2; kk++) {
            uint32_t ah[4][4], al[4][4];
            #pragma unroll
            for (int mt = 0; mt < 4; mt++) {
                uint32_t ad = sb + s * GST + kk * GA_CH +
                              (uint32_t)(wr * 64 + mt * 16 + arow) * 48 + ahalf * 16;
                ldsm4(ah[mt], ad);
                ldsm4(al[mt], ad + GA_HL);
            }
            uint32_t bh[4][4], bl[4][4];
            #pragma unroll
            for (int p = 0; p < 4; p++) {
                uint32_t bd = sb + s * GST + 2 * GA_HL + kk * GB_CH +
                              (uint32_t)(wc * 64 + p * 16 + brow) * 48 + bhalf * 16;
                ldsm4(bh[p], bd);
                ldsm4(bl[p], bd + GB_HL);
            }
            #pragma unroll
            for (int mt = 0; mt < 4; mt++)
                #pragma unroll
                for (int nt = 0; nt < 8; nt++) {
                    int p = nt >> 1, i0 = (nt & 1) * 2;
                    mma16816(acc[mt][nt], ah[mt], bh[p][i0], bh[p][i0 + 1]);
                    mma16816(acc[mt][nt], ah[mt], bl[p][i0], bl[p][i0 + 1]);
                    mma16816(acc[mt][nt], al[mt], bh[p][i0], bh[p][i0 + 1]);
                }
        }
        __syncthreads();
    }

    #pragma unroll
    for (int mt = 0; mt < 4; mt++) {
        int r0 = m0 + wr * 64 + mt * 16 + (lane >> 2);
        #pragma unroll
        for (int nt = 0; nt < 8; nt++) {
            int nglob = n0 + wc * 64 + nt * 8 + (lane & 3) * 2;
            if (MODE == 0) {
                int z = nglob >> 9;
                int nn = nglob & 511;
                int h = nn >> 6, dh = nn & 63;
                const float* bias = (z == 0) ? b0 : (z == 1) ? b1 : b2;
                bf16* OH = (z == 0) ? oh0 : (z == 1) ? oh1 : oh2;
                bf16* OL = (z == 0) ? ol0 : (z == 1) ? ol1 : ol2;
                float bv0 = bias[nn], bv1 = bias[nn + 1];
                #pragma unroll
                for (int j = 0; j < 2; j++) {
                    int r = r0 + j * 8;
                    int bb = r >> 11, sidx = r & 2047;
                    size_t dst = ((size_t)((bb * N_HEADS + h) * SEQ + sidx)) * D_HEAD + dh;
                    float v0 = acc[mt][nt][2 * j] + bv0;
                    float v1 = acc[mt][nt][2 * j + 1] + bv1;
                    uint32_t hp, lp;
                    split_pack(v0, v1, hp, lp);
                    *(uint32_t*)(OH + dst) = hp;
                    *(uint32_t*)(OL + dst) = lp;
                }
            } else if (MODE == 1) {
                float bv0 = b0[nglob], bv1 = b0[nglob + 1];
                #pragma unroll
                for (int j = 0; j < 2; j++) {
                    int r = r0 + j * 8;
                    size_t dst = (size_t)r * D_FF + nglob;
                    float v0 = fmaxf(acc[mt][nt][2 * j] + bv0, 0.f);
                    float v1 = fmaxf(acc[mt][nt][2 * j + 1] + bv1, 0.f);
                    uint32_t hp, lp;
                    split_pack(v0, v1, hp, lp);
                    *(uint32_t*)(oh0 + dst) = hp;
                    *(uint32_t*)(ol0 + dst) = lp;
                }
            } else {
                float bv0 = b0[nglob], bv1 = b0[nglob + 1];
                #pragma unroll
                for (int j = 0; j < 2; j++) {
                    int r = r0 + j * 8;
                    size_t dst = (size_t)r * D_MODEL + nglob;
                    float2 rv = *(const float2*)(res + dst);
                    float2 ov;
                    ov.x = acc[mt][nt][2 * j] + bv0 + rv.x;
                    ov.y = acc[mt][nt][2 * j + 1] + bv1 + rv.y;
                    *(float2*)(o32 + dst) = ov;
                }
            }
        }
    }
}

// ---------------- fused sigmoid attention: register S-reuse (unchanged) ----------------
#define AKCH  (64 * 48)
#define AKMAT (4 * AKCH)
#define AKSTG (4 * AKMAT)
#define AQOFF (2 * AKSTG)
#define AQCH  (128 * 48)
#define AQMAT (4 * AQCH)
#define ASMEM (AQOFF + 2 * AQMAT)    // 147456
#define ATT_HSCALE 0.022097086912079608f

__global__ void __launch_bounds__(256) attn_kernel(
    const bf16* __restrict__ Qh, const bf16* __restrict__ Ql,
    const bf16* __restrict__ Kh, const bf16* __restrict__ Kl,
    const bf16* __restrict__ Vh, const bf16* __restrict__ Vl,
    float* __restrict__ O)
{
    extern __shared__ char smem[];
    uint32_t sb = smem_u32(smem);
    int tid = threadIdx.x, wid = tid >> 5, lane = tid & 31;
    int wq = wid >> 1, wk = wid & 1;
    int bh = blockIdx.y;
    int q0 = blockIdx.x * 128;
    size_t bhbase = (size_t)bh * SEQ * D_HEAD;

    {
        const bf16* qs[2] = {Qh, Ql};
        #pragma unroll
        for (int i = 0; i < 8; i++) {
            int idx = i * 256 + tid;
            int mat = idx >> 10;
            int rem = idx & 1023;
            int row = rem >> 3;
            int q = rem & 7, cc = q >> 1, half = q & 1;
            const bf16* src = qs[mat] + bhbase + (size_t)(q0 + row) * D_HEAD + cc * 16 + half * 8;
            uint32_t dst = sb + AQOFF + mat * AQMAT + cc * AQCH + row * 48 + half * 16;
            cp16(dst, src);
        }
    }

    const bf16* kvs[4] = {Kh, Kl, Vh, Vl};
    auto load_kv = [&](int t0, int s) {
        #pragma unroll
        for (int i = 0; i < 8; i++) {
            int idx = i * 256 + tid;
            int mat = idx >> 9;
            int rem = idx & 511;
            int row = rem >> 3;
            int q = rem & 7, cc = q >> 1, half = q & 1;
            const bf16* src = kvs[mat] + bhbase + (size_t)(t0 + row) * D_HEAD + cc * 16 + half * 8;
            uint32_t dst = sb + s * AKSTG + mat * AKMAT + cc * AKCH + row * 48 + half * 16;
            cp16(dst, src);
        }
    };

    load_kv(0, 0);
    CP_COMMIT();

    float oacc[2][8][4];
    #pragma unroll
    for (int a = 0; a < 2; a++)
        #pragma unroll
        for (int b = 0; b < 8; b++)
            #pragma unroll
            for (int cc = 0; cc < 4; cc++) oacc[a][b][cc] = 0.f;

    int arow = lane & 15, ahalf = lane >> 4;
    int brow = (lane & 7) + ((lane >> 4) << 3), bhalf = (lane >> 3) & 1;
    const int niter = SEQ / 64;
    for (int c = 0; c < niter; c++) {
        int s = c & 1;
        if (c + 1 < niter) { load_kv((c + 1) * 64, s ^ 1); CP_COMMIT(); CP_WAIT1(); }
        else CP_WAIT0();
        __syncthreads();

        float sacc[2][4][4];
        #pragma unroll
        for (int a = 0; a < 2; a++)
            #pragma unroll
            for (int b = 0; b < 4; b++)
                #pragma unroll
                for (int cc = 0; cc < 4; cc++) sacc[a][b][cc] = 0.f;

        #pragma unroll
        for (int cc = 0; cc < 4; cc++) {
            uint32_t qah[2][4], qal[2][4];
            #pragma unroll
            for (int mt = 0; mt < 2; mt++) {
                uint32_t ad = sb + AQOFF + cc * AQCH +
                              (uint32_t)(wq * 32 + mt * 16 + arow) * 48 + ahalf * 16;
                ldsm4(qah[mt], ad);
                ldsm4(qal[mt], ad + AQMAT);
            }
            uint32_t kbh[2][4], kbl[2][4];
            #pragma unroll
            for (int p = 0; p < 2; p++) {
                uint32_t bd = sb + s * AKSTG + cc * AKCH +
                              (uint32_t)(wk * 32 + p * 16 + brow) * 48 + bhalf * 16;
                ldsm4(kbh[p], bd);
                ldsm4(kbl[p], bd + AKMAT);
            }
            #pragma unroll
            for (int mt = 0; mt < 2; mt++)
                #pragma unroll
                for (int nt = 0; nt < 4; nt++) {
                    int p = nt >> 1, i0 = (nt & 1) * 2;
                    mma16816(sacc[mt][nt], qah[mt], kbh[p][i0], kbh[p][i0 + 1]);
                    mma16816(sacc[mt][nt], qah[mt], kbl[p][i0], kbl[p][i0 + 1]);
                    mma16816(sacc[mt][nt], qal[mt], kbh[p][i0], kbh[p][i0 + 1]);
                }
        }

        #pragma unroll
        for (int mt = 0; mt < 2; mt++)
            #pragma unroll
            for (int nt = 0; nt < 4; nt++)
                #pragma unroll
                for (int i = 0; i < 4; i++)
                    sacc[mt][nt][i] = sigmoid_fast(sacc[mt][nt][i] * ATT_HSCALE);

        // A-frag order: a0=(row,k0-7), a1=(row+8,k0-7), a2=(row,k8-15), a3=(row+8,k8-15)
        uint32_t Sh[2][2][4], Sl[2][2][4];
        #pragma unroll
        for (int mt = 0; mt < 2; mt++)
            #pragma unroll
            for (int kc = 0; kc < 2; kc++) {
                split_pack(sacc[mt][2*kc][0],   sacc[mt][2*kc][1],   Sh[mt][kc][0], Sl[mt][kc][0]);
                split_pack(sacc[mt][2*kc][2],   sacc[mt][2*kc][3],   Sh[mt][kc][1], Sl[mt][kc][1]);
                split_pack(sacc[mt][2*kc+1][0], sacc[mt][2*kc+1][1], Sh[mt][kc][2], Sl[mt][kc][2]);
                split_pack(sacc[mt][2*kc+1][2], sacc[mt][2*kc+1][3], Sh[mt][kc][3], Sl[mt][kc][3]);
            }

        #pragma unroll
        for (int kc = 0; kc < 2; kc++) {
            #pragma unroll
            for (int dg = 0; dg < 4; dg++) {
                uint32_t vbh[4], vbl[4];
                uint32_t vad = sb + s * AKSTG + 2 * AKMAT + dg * AKCH +
                               (uint32_t)(wk * 32 + kc * 16 + (lane & 15)) * 48 + (lane >> 4) * 16;
                ldsm4t(vbh, vad);
                ldsm4t(vbl, vad + AKMAT);
                #pragma unroll
                for (int mt = 0; mt < 2; mt++)
                    #pragma unroll
                    for (int nt2 = 0; nt2 < 2; nt2++) {
                        float* o = oacc[mt][dg * 2 + nt2];
                        mma16816(o, Sh[mt][kc], vbh[nt2 * 2], vbh[nt2 * 2 + 1]);
                        mma16816(o, Sh[mt][kc], vbl[nt2 * 2], vbl[nt2 * 2 + 1]);
                        mma16816(o, Sl[mt][kc], vbh[nt2 * 2], vbh[nt2 * 2 + 1]);
                    }
            }
        }
        __syncthreads();
    }

    if (wk == 1) {
        #pragma unroll
        for (int mt = 0; mt < 2; mt++)
            #pragma unroll
            for (int nt = 0; nt < 8; nt++)
                #pragma unroll
                for (int j = 0; j < 2; j++) {
                    int r = mt * 16 + (lane >> 2) + j * 8;
                    int col = nt * 8 + (lane & 3) * 2;
                    float2 p; p.x = oacc[mt][nt][2 * j]; p.y = oacc[mt][nt][2 * j + 1];
                    *(float2*)(smem + wq * 8192 + r * 256 + col * 4) = p;
                }
    }
    __syncthreads();
    if (wk == 0) {
        int b = bh >> 3, h = bh & 7;
        #pragma unroll
        for (int mt = 0; mt < 2; mt++)
            #pragma unroll
            for (int nt = 0; nt < 8; nt++)
                #pragma unroll
                for (int j = 0; j < 2; j++) {
                    int r = mt * 16 + (lane >> 2) + j * 8;
                    int col = nt * 8 + (lane & 3) * 2;
                    float2 p = *(const float2*)(smem + wq * 8192 + r * 256 + col * 4);
                    float2 o;
                    o.x = oacc[mt][nt][2 * j] + p.x;
                    o.y = oacc[mt][nt][2 * j + 1] + p.y;
                    *(float2*)(O + (size_t)(b * SEQ + q0 + wq * 32 + r) * D_MODEL + h * D_HEAD + col) = o;
                }
    }
}

// ---------------- launch ----------------
extern "C" void kernel_launch(void* const* d_in, const int* in_sizes, int n_in,
                              void* d_out, int out_size) {
    const float* x   = (const float*)d_in[0];
    const float* Wq  = (const float*)d_in[1];
    const float* bq  = (const float*)d_in[2];
    const float* Wk  = (const float*)d_in[3];
    const float* bk  = (const float*)d_in[4];
    const float* Wv  = (const float*)d_in[5];
    const float* bv  = (const float*)d_in[6];
    const float* W1  = (const float*)d_in[7];
    const float* b1  = (const float*)d_in[8];
    const float* W2  = (const float*)d_in[9];
    const float* b2  = (const float*)d_in[10];
    const float* g1  = (const float*)d_in[11];
    const float* be1 = (const float*)d_in[12];
    const float* g2  = (const float*)d_in[13];
    const float* be2 = (const float*)d_in[14];
    float* out = (float*)d_out;

    bf16 *p_xh, *p_xl, *p_x2h, *p_x2l, *p_fh, *p_fl;
    bf16 *p_qh, *p_ql, *p_kh, *p_kl, *p_vh, *p_vl;
    bf16 *p_wqh, *p_wql, *p_w1h, *p_w1l, *p_w2h, *p_w2l;
    float *p_attn, *p_x2;
    cudaGetSymbolAddress((void**)&p_xh, g_xh);
    cudaGetSymbolAddress((void**)&p_xl, g_xl);
    cudaGetSymbolAddress((void**)&p_qh, g_qh);
    cudaGetSymbolAddress((void**)&p_ql, g_ql);
    cudaGetSymbolAddress((void**)&p_kh, g_kh);
    cudaGetSymbolAddress((void**)&p_kl, g_kl);
    cudaGetSymbolAddress((void**)&p_vh, g_vh);
    cudaGetSymbolAddress((void**)&p_vl, g_vl);
    cudaGetSymbolAddress((void**)&p_attn, g_attn);
    cudaGetSymbolAddress((void**)&p_x2, g_x2);
    cudaGetSymbolAddress((void**)&p_x2h, g_x2h);
    cudaGetSymbolAddress((void**)&p_x2l, g_x2l);
    cudaGetSymbolAddress((void**)&p_fh, g_fh);
    cudaGetSymbolAddress((void**)&p_fl, g_fl);
    cudaGetSymbolAddress((void**)&p_wqh, g_wqh);
    cudaGetSymbolAddress((void**)&p_wql, g_wql);
    cudaGetSymbolAddress((void**)&p_w1h, g_w1h);
    cudaGetSymbolAddress((void**)&p_w1l, g_w1l);
    cudaGetSymbolAddress((void**)&p_w2h, g_w2h);
    cudaGetSymbolAddress((void**)&p_w2l, g_w2l);

    cudaFuncSetAttribute(mma_gemm_kernel<0>, cudaFuncAttributeMaxDynamicSharedMemorySize, GSMEM);
    cudaFuncSetAttribute(mma_gemm_kernel<1>, cudaFuncAttributeMaxDynamicSharedMemorySize, GSMEM);
    cudaFuncSetAttribute(mma_gemm_kernel<2>, cudaFuncAttributeMaxDynamicSharedMemorySize, GSMEM);
    cudaFuncSetAttribute(attn_kernel, cudaFuncAttributeMaxDynamicSharedMemorySize, ASMEM);

    // 0. fused weight transpose+split (one launch)
    transpose_split_all_kernel<<<2816, dim3(32, 8)>>>(
        Wq, Wk, Wv, W1, W2, p_wqh, p_wql, p_w1h, p_w1l, p_w2h, p_w2l);
    // 1. LN1 -> bf16 hi/lo
    ln_kernel<<<M_TOTAL, 128>>>(x, g1, be1, p_xh, p_xl);
    // 2. QKV: bf16 hi/lo head-permuted outputs (N total 1536 -> 6 x-blocks)
    mma_gemm_kernel<0><<<dim3(3*D_MODEL/256, M_TOTAL/128), 256, GSMEM>>>(
        p_xh, p_xl, p_wqh, p_wql, D_MODEL, bq, bk, bv, nullptr, nullptr,
        p_qh, p_ql, p_kh, p_kl, p_vh, p_vl);
    // 3. fused sigmoid attention (register S-reuse)
    attn_kernel<<<dim3(SEQ/128, BH), 256, ASMEM>>>(
        p_qh, p_ql, p_kh, p_kl, p_vh, p_vl, p_attn);
    // 4. residual + LN2
    addln_kernel<<<M_TOTAL, 128>>>(x, p_attn, g2, be2, p_x2, p_x2h, p_x2l);
    // 5. FFN1: relu(xn2 @ W1 + b1) -> bf16 hi/lo   [ncu -s 5 lands here]
    mma_gemm_kernel<1><<<dim3(D_FF/256, M_TOTAL/128), 256, GSMEM>>>(
        p_x2h, p_x2l, p_w1h, p_w1l, D_MODEL, b1, nullptr, nullptr, nullptr, nullptr,
        p_fh, p_fl, nullptr, nullptr, nullptr, nullptr);
    // 6. FFN2: ffh @ W2 + b2 + x2 -> out
    mma_gemm_kernel<2><<<dim3(D_MODEL/256, M_TOTAL/128), 256, GSMEM>>>(
        p_fh, p_fl, p_w2h, p_w2l, D_FF, b2, nullptr, nullptr, p_x2, out,
        nullptr, nullptr, nullptr, nullptr, nullptr, nullptr);
}